// round 1
// baseline (speedup 1.0000x reference)
#include <cuda_runtime.h>
#include <math.h>

// Problem constants
#define NB 4
#define NS 1024
#define NE 2048
#define NH 16
#define ND 128
#define ATTN_SCALE 0.08838834764831845f  // 1/sqrt(128)

// Scratch (static __device__ arrays per harness rules)
__device__ float g_q  [(size_t)NB * NH * NS * ND];          // [b,h,s,d]
__device__ float g_k  [(size_t)NB * NH * NS * ND];          // [b,h,s,d]
__device__ float g_vT [(size_t)NB * NH * ND * NS];          // [b,h,d,s]  (transposed V)
__device__ float g_sc [(size_t)NB * NH * NS * NS];          // [b,h,q,k]  scores (256 MB)
__device__ float g_ctx[(size_t)NB * NS * NE];               // [b,s,e]

// ---------------------------------------------------------------------------
// Generic TN GEMM: C[m,n] = sum_k A[m,k] * B[n,k]   (both row-major, lda=ldb=K)
// 128x128 tile, BK=16, 256 threads, 8x8 per-thread microtile.
// Param struct P supplies batch base pointers and the epilogue store.
// ---------------------------------------------------------------------------
template <class P>
__global__ __launch_bounds__(256) void gemm_tn(P p, int K)
{
    constexpr int BM = 128, BN = 128, BK = 16;
    __shared__ float As[BK][BM + 4];
    __shared__ float Bs[BK][BN + 4];

    const int bz = blockIdx.z;
    const float* A  = p.Aptr(bz) + (size_t)blockIdx.y * BM * K;
    const float* Bm = p.Bptr(bz) + (size_t)blockIdx.x * BN * K;

    const int tid = threadIdx.x;
    const int tx = tid & 15;        // 0..15 (n)
    const int ty = tid >> 4;        // 0..15 (m)
    const int lr = tid >> 2;        // 0..63 load row
    const int lc = (tid & 3) << 2;  // 0,4,8,12 load col

    float acc[8][8] = {};

    for (int kt = 0; kt < K; kt += BK) {
        float4 a0 = *(const float4*)(A  + (size_t)lr        * K + kt + lc);
        float4 a1 = *(const float4*)(A  + (size_t)(lr + 64) * K + kt + lc);
        float4 b0 = *(const float4*)(Bm + (size_t)lr        * K + kt + lc);
        float4 b1 = *(const float4*)(Bm + (size_t)(lr + 64) * K + kt + lc);

        __syncthreads();
        As[lc + 0][lr] = a0.x; As[lc + 1][lr] = a0.y;
        As[lc + 2][lr] = a0.z; As[lc + 3][lr] = a0.w;
        As[lc + 0][lr + 64] = a1.x; As[lc + 1][lr + 64] = a1.y;
        As[lc + 2][lr + 64] = a1.z; As[lc + 3][lr + 64] = a1.w;
        Bs[lc + 0][lr] = b0.x; Bs[lc + 1][lr] = b0.y;
        Bs[lc + 2][lr] = b0.z; Bs[lc + 3][lr] = b0.w;
        Bs[lc + 0][lr + 64] = b1.x; Bs[lc + 1][lr + 64] = b1.y;
        Bs[lc + 2][lr + 64] = b1.z; Bs[lc + 3][lr + 64] = b1.w;
        __syncthreads();

#pragma unroll
        for (int kk = 0; kk < BK; ++kk) {
            float rA[8], rB[8];
            *(float4*)&rA[0] = *(const float4*)&As[kk][ty * 8];
            *(float4*)&rA[4] = *(const float4*)&As[kk][ty * 8 + 4];
            *(float4*)&rB[0] = *(const float4*)&Bs[kk][tx * 8];
            *(float4*)&rB[4] = *(const float4*)&Bs[kk][tx * 8 + 4];
#pragma unroll
            for (int i = 0; i < 8; ++i)
#pragma unroll
                for (int j = 0; j < 8; ++j)
                    acc[i][j] += rA[i] * rB[j];
        }
    }

    p.store(bz, blockIdx.y * BM + ty * 8, blockIdx.x * BN + tx * 8, acc);
}

// ---- Epilogue / source param structs ------------------------------------

// 1) QKV projection: A=query[4096,2048], B=in_proj_weight[6144,2048].
//    Fused bias + scatter to per-head layouts (V transposed).
struct PQkv {
    const float* x;
    const float* w;
    const float* bias;
    __device__ const float* Aptr(int) const { return x; }
    __device__ const float* Bptr(int) const { return w; }
    __device__ void store(int, int m0, int n0, const float acc[8][8]) const {
#pragma unroll
        for (int i = 0; i < 8; ++i) {
            const int m = m0 + i;
            const int b = m >> 10;
            const int s = m & 1023;
#pragma unroll
            for (int j = 0; j < 8; ++j) {
                const int f = n0 + j;
                const float v = acc[i][j] + bias[f];
                const int which = f >> 11;   // 0=Q 1=K 2=V
                const int e = f & 2047;
                const int h = e >> 7;
                const int d = e & 127;
                if (which == 0) {
                    g_q[((size_t)((b * NH + h) * NS + s)) * ND + d] = v;
                } else if (which == 1) {
                    g_k[((size_t)((b * NH + h) * NS + s)) * ND + d] = v;
                } else {
                    g_vT[((size_t)((b * NH + h) * ND + d)) * NS + s] = v;
                }
            }
        }
    }
};

// 2) scores = (Q @ K^T) * scale, batched over bz = b*NH + h.
struct PScores {
    __device__ const float* Aptr(int bz) const { return g_q + (size_t)bz * NS * ND; }
    __device__ const float* Bptr(int bz) const { return g_k + (size_t)bz * NS * ND; }
    __device__ void store(int bz, int m0, int n0, const float acc[8][8]) const {
        float* dst = g_sc + (size_t)bz * NS * NS;
#pragma unroll
        for (int i = 0; i < 8; ++i) {
            float* row = dst + (size_t)(m0 + i) * NS + n0;
#pragma unroll
            for (int j = 0; j < 8; ++j) row[j] = acc[i][j] * ATTN_SCALE;
        }
    }
};

// 4) ctx = P @ V  (A = softmaxed scores [1024,1024], B = vT [128,1024])
struct PCtx {
    __device__ const float* Aptr(int bz) const { return g_sc  + (size_t)bz * NS * NS; }
    __device__ const float* Bptr(int bz) const { return g_vT  + (size_t)bz * ND * NS; }
    __device__ void store(int bz, int m0, int n0, const float acc[8][8]) const {
        const int b = bz >> 4;
        const int h = bz & 15;
#pragma unroll
        for (int i = 0; i < 8; ++i) {
            float* row = g_ctx + ((size_t)(b * NS + (m0 + i))) * NE + h * ND + n0;
#pragma unroll
            for (int j = 0; j < 8; ++j) row[j] = acc[i][j];
        }
    }
};

// 5) out = ctx @ W_out^T + bias
struct POut {
    const float* w;
    const float* bias;
    float* out;
    __device__ const float* Aptr(int) const { return g_ctx; }
    __device__ const float* Bptr(int) const { return w; }
    __device__ void store(int, int m0, int n0, const float acc[8][8]) const {
#pragma unroll
        for (int i = 0; i < 8; ++i) {
            float* row = out + (size_t)(m0 + i) * NE + n0;
#pragma unroll
            for (int j = 0; j < 8; ++j) row[j] = acc[i][j] + bias[n0 + j];
        }
    }
};

// ---------------------------------------------------------------------------
// 3) Row softmax over 1024 elements. One block per row, values stay in regs.
// ---------------------------------------------------------------------------
__global__ __launch_bounds__(256) void softmax_k()
{
    const size_t row = blockIdx.x;
    float* p = g_sc + row * NS;
    const int t = threadIdx.x;

    float4 v = reinterpret_cast<float4*>(p)[t];

    __shared__ float red[8];

    // block max
    float mx = fmaxf(fmaxf(v.x, v.y), fmaxf(v.z, v.w));
#pragma unroll
    for (int o = 16; o > 0; o >>= 1)
        mx = fmaxf(mx, __shfl_xor_sync(0xffffffffu, mx, o));
    if ((t & 31) == 0) red[t >> 5] = mx;
    __syncthreads();
    float M = red[0];
#pragma unroll
    for (int w = 1; w < 8; ++w) M = fmaxf(M, red[w]);
    __syncthreads();  // protect red before reuse

    // exp + block sum
    v.x = expf(v.x - M);
    v.y = expf(v.y - M);
    v.z = expf(v.z - M);
    v.w = expf(v.w - M);
    float s = (v.x + v.y) + (v.z + v.w);
#pragma unroll
    for (int o = 16; o > 0; o >>= 1)
        s += __shfl_xor_sync(0xffffffffu, s, o);
    if ((t & 31) == 0) red[t >> 5] = s;
    __syncthreads();
    float S = red[0];
#pragma unroll
    for (int w = 1; w < 8; ++w) S += red[w];

    const float inv = 1.0f / S;
    v.x *= inv; v.y *= inv; v.z *= inv; v.w *= inv;
    reinterpret_cast<float4*>(p)[t] = v;
}

// ---------------------------------------------------------------------------
extern "C" void kernel_launch(void* const* d_in, const int* in_sizes, int n_in,
                              void* d_out, int out_size)
{
    (void)in_sizes; (void)n_in; (void)out_size;
    const float* x  = (const float*)d_in[0];  // query [4,1024,2048]
    const float* wi = (const float*)d_in[1];  // in_proj_weight [6144,2048]
    const float* bi = (const float*)d_in[2];  // in_proj_bias [6144]
    const float* wo = (const float*)d_in[3];  // out_proj_weight [2048,2048]
    const float* bo = (const float*)d_in[4];  // out_proj_bias [2048]
    float* out = (float*)d_out;               // [4,1024,2048]

    // 1) QKV projection + bias + head scatter
    gemm_tn<<<dim3(6144 / 128, 4096 / 128, 1), 256>>>(PQkv{x, wi, bi}, NE);

    // 2) scores = Q K^T * scale, batched over 64 (b,h)
    gemm_tn<<<dim3(NS / 128, NS / 128, NB * NH), 256>>>(PScores{}, ND);

    // 3) softmax rows
    softmax_k<<<NB * NH * NS, 256>>>();

    // 4) ctx = P V
    gemm_tn<<<dim3(ND / 128, NS / 128, NB * NH), 256>>>(PCtx{}, NS);

    // 5) output projection + bias
    gemm_tn<<<dim3(NE / 128, 4096 / 128, 1), 256>>>(POut{wo, bo, out}, NE);
}

// round 6
// speedup vs baseline: 2.0844x; 2.0844x over previous
#include <cuda_runtime.h>
#include <cuda_bf16.h>
#include <math.h>
#include <stdint.h>

#define NB 4
#define NS 1024
#define NE 2048
#define NH 16
#define ND 128
#define ATTN_SCALE 0.08838834764831845f

typedef __nv_bfloat16 bf16;

// ---------------- scratch (device globals; referenced ONLY from device code) --
__device__ __align__(256) bf16 g_xh [(size_t)NB*NS*NE];
__device__ __align__(256) bf16 g_xl [(size_t)NB*NS*NE];
__device__ __align__(256) bf16 g_wih[(size_t)3*NE*NE];
__device__ __align__(256) bf16 g_wil[(size_t)3*NE*NE];
__device__ __align__(256) bf16 g_woh[(size_t)NE*NE];
__device__ __align__(256) bf16 g_wol[(size_t)NE*NE];
__device__ __align__(256) bf16 g_qh [(size_t)NB*NH*NS*ND];
__device__ __align__(256) bf16 g_ql [(size_t)NB*NH*NS*ND];
__device__ __align__(256) bf16 g_kh [(size_t)NB*NH*NS*ND];
__device__ __align__(256) bf16 g_kl [(size_t)NB*NH*NS*ND];
__device__ __align__(256) bf16 g_vTh[(size_t)NB*NH*ND*NS];   // [b,h,d,s]
__device__ __align__(256) bf16 g_vTl[(size_t)NB*NH*ND*NS];
__device__ __align__(256) float g_sc[(size_t)NB*NH*NS*NS];
__device__ __align__(256) bf16 g_ph [(size_t)NB*NH*NS*NS];
__device__ __align__(256) bf16 g_pl [(size_t)NB*NH*NS*NS];
__device__ __align__(256) bf16 g_ch [(size_t)NB*NS*NE];
__device__ __align__(256) bf16 g_cl [(size_t)NB*NS*NE];

// ---------------- PTX helpers ------------------------------------------------
__device__ __forceinline__ uint32_t smem_u32(const void* p) {
    uint32_t a;
    asm("{ .reg .u64 t; cvta.to.shared.u64 t, %1; cvt.u32.u64 %0, t; }" : "=r"(a) : "l"(p));
    return a;
}

#define CP16(dst, src) \
    asm volatile("cp.async.cg.shared.global [%0], [%1], 16;" :: "r"(dst), "l"(src) : "memory")
#define CP_COMMIT() asm volatile("cp.async.commit_group;" ::: "memory")
#define CP_WAIT1()  asm volatile("cp.async.wait_group 1;" ::: "memory")
#define CP_WAIT0()  asm volatile("cp.async.wait_group 0;" ::: "memory")

__device__ __forceinline__ void mma16816(float* d, const uint32_t* a, uint32_t b0, uint32_t b1) {
    asm volatile(
        "mma.sync.aligned.m16n8k16.row.col.f32.bf16.bf16.f32 "
        "{%0,%1,%2,%3}, {%4,%5,%6,%7}, {%8,%9}, {%0,%1,%2,%3};"
        : "+f"(d[0]), "+f"(d[1]), "+f"(d[2]), "+f"(d[3])
        : "r"(a[0]), "r"(a[1]), "r"(a[2]), "r"(a[3]), "r"(b0), "r"(b1));
}

__device__ __forceinline__ uint32_t pk(bf16 a, bf16 b) {
    return (uint32_t)__bfloat16_as_ushort(a) | ((uint32_t)__bfloat16_as_ushort(b) << 16);
}
__device__ __forceinline__ void split(float v, bf16& h, bf16& l) {
    h = __float2bfloat16(v);
    l = __float2bfloat16(v - __bfloat162float(h));
}

// ---------------- operand-source / epilogue param structs -------------------
// ptr(w, bz): w=0 Ah, 1 Al, 2 Bh, 3 Bl.  All operands are [rows][K] row-major.
// Globals resolved in DEVICE code only; structs carry no device-global addrs.
struct PQkv {
    const float* bias;
    __device__ const bf16* ptr(int w, int) const {
        return w == 0 ? g_xh : w == 1 ? g_xl : w == 2 ? g_wih : g_wil;
    }
    __device__ __forceinline__ void store2(int, int m, int n, float v0, float v1) const {
        v0 += bias[n]; v1 += bias[n + 1];
        bf16 h0, l0, h1, l1;
        split(v0, h0, l0); split(v1, h1, l1);
        const int which = n >> 11;
        const int e = n & 2047, h = e >> 7, d = e & 127;
        const int b = m >> 10, s = m & 1023;
        if (which < 2) {
            bf16* dh = which == 0 ? g_qh : g_kh;
            bf16* dl = which == 0 ? g_ql : g_kl;
            const size_t off = ((size_t)((b * NH + h) * NS + s)) * ND + d;
            *(uint32_t*)(dh + off) = pk(h0, h1);
            *(uint32_t*)(dl + off) = pk(l0, l1);
        } else {
            // V stored transposed: [b,h,d,s]; pair (d, d+1) -> two rows, same col s
            const size_t off = ((size_t)((b * NH + h) * ND + d)) * NS + s;
            g_vTh[off]      = h0;  g_vTh[off + NS] = h1;
            g_vTl[off]      = l0;  g_vTl[off + NS] = l1;
        }
    }
};

struct PScores {
    __device__ const bf16* ptr(int w, int bz) const {
        const size_t o = (size_t)bz * NS * ND;
        return w == 0 ? g_qh + o : w == 1 ? g_ql + o : w == 2 ? g_kh + o : g_kl + o;
    }
    __device__ __forceinline__ void store2(int bz, int m, int n, float v0, float v1) const {
        float2 o = make_float2(v0 * ATTN_SCALE, v1 * ATTN_SCALE);
        *(float2*)(g_sc + ((size_t)bz << 20) + (size_t)m * NS + n) = o;
    }
};

struct PCtx {
    __device__ const bf16* ptr(int w, int bz) const {
        const size_t op = (size_t)bz * NS * NS;
        const size_t ov = (size_t)bz * ND * NS;
        return w == 0 ? g_ph + op : w == 1 ? g_pl + op : w == 2 ? g_vTh + ov : g_vTl + ov;
    }
    __device__ __forceinline__ void store2(int bz, int m, int n, float v0, float v1) const {
        const int b = bz >> 4, h = bz & 15;
        bf16 h0, l0, h1, l1;
        split(v0, h0, l0); split(v1, h1, l1);
        const size_t off = (size_t)(b * NS + m) * NE + h * ND + n;
        *(uint32_t*)(g_ch + off) = pk(h0, h1);
        *(uint32_t*)(g_cl + off) = pk(l0, l1);
    }
};

struct POut {
    const float* bias;
    float* out;
    __device__ const bf16* ptr(int w, int) const {
        return w == 0 ? g_ch : w == 1 ? g_cl : w == 2 ? g_woh : g_wol;
    }
    __device__ __forceinline__ void store2(int, int m, int n, float v0, float v1) const {
        float2 o = make_float2(v0 + bias[n], v1 + bias[n + 1]);
        *(float2*)(out + (size_t)m * NE + n) = o;
    }
};

// ---------------- split-bf16 MMA GEMM ----------------------------------------
// C[128,128] = Ah·Bh^T + Al·Bh^T + Ah·Bl^T, fp32 accum.
// All operands [rows][K] row-major. BK=16. smem tile: 128 rows x 48B pitch
// (32B data + 16B pad). 4 tiles/stage (Ah,Al,Bh,Bl) = 24KB; double-buffered
// = 49152B STATIC shared (no opt-in). Direct per-thread fragment LDS.
#define SLOT   6144u
#define STAGE  24576u

template <class P>
__global__ __launch_bounds__(256) void gemm_mma(P p, int K)
{
    __shared__ __align__(1024) char smem[2 * STAGE];
    const uint32_t sb = smem_u32(smem);
    const int tid  = threadIdx.x;
    const int lane = tid & 31, wid = tid >> 5;
    const int wm = wid >> 1, wn = wid & 1;       // 4x2 warp grid, warp tile 32x64
    const int gid = lane >> 2, tig = lane & 3;   // fragment coords
    const int bz = blockIdx.z;
    const int m0 = blockIdx.y * 128, n0 = blockIdx.x * 128;

    const bf16* ap[2] = { p.ptr(0, bz), p.ptr(1, bz) };
    const bf16* bp[2] = { p.ptr(2, bz), p.ptr(3, bz) };

    const int r = tid >> 1, cc = tid & 1;        // 128 rows x 2 16B-chunks

    auto issue = [&](int st, int kt) {
        const uint32_t s = sb + (uint32_t)st * STAGE;
#pragma unroll
        for (int t = 0; t < 2; ++t)
            CP16(s + t * SLOT + (uint32_t)(r * 48 + cc * 16),
                 ap[t] + (size_t)(m0 + r) * K + kt + cc * 8);
#pragma unroll
        for (int t = 0; t < 2; ++t)
            CP16(s + (2 + t) * SLOT + (uint32_t)(r * 48 + cc * 16),
                 bp[t] + (size_t)(n0 + r) * K + kt + cc * 8);
    };

    float acc[2][8][4];
#pragma unroll
    for (int i = 0; i < 2; ++i)
#pragma unroll
        for (int j = 0; j < 8; ++j)
#pragma unroll
            for (int q = 0; q < 4; ++q) acc[i][j][q] = 0.0f;

    issue(0, 0);
    CP_COMMIT();

    const int NC = K >> 4;
    for (int c = 0; c < NC; ++c) {
        if (c + 1 < NC) { issue((c + 1) & 1, (c + 1) << 4); CP_COMMIT(); CP_WAIT1(); }
        else            { CP_WAIT0(); }
        __syncthreads();

        const char* stg = smem + (size_t)(c & 1) * STAGE;
        const int kb = tig * 4;  // byte offset of this thread's k-pair (2 elems)

        // A fragments: a0=(row g, k0..1) a1=(g+8) a2=(g, k+8) a3=(g+8, k+8)
        uint32_t ah[2][4], al[2][4];
#pragma unroll
        for (int mi = 0; mi < 2; ++mi) {
            const char* pa = stg + (wm * 32 + mi * 16 + gid) * 48 + kb;
            ah[mi][0] = *(const uint32_t*)(pa);
            ah[mi][1] = *(const uint32_t*)(pa + 8 * 48);
            ah[mi][2] = *(const uint32_t*)(pa + 16);
            ah[mi][3] = *(const uint32_t*)(pa + 8 * 48 + 16);
            al[mi][0] = *(const uint32_t*)(pa + SLOT);
            al[mi][1] = *(const uint32_t*)(pa + SLOT + 8 * 48);
            al[mi][2] = *(const uint32_t*)(pa + SLOT + 16);
            al[mi][3] = *(const uint32_t*)(pa + SLOT + 8 * 48 + 16);
        }

        // B fragments per 8-col block: b0=(n g, k0..1), b1=(n g, k+8)
        uint32_t bh[4][2][2], bl[4][2][2];
#pragma unroll
        for (int ni = 0; ni < 4; ++ni)
#pragma unroll
            for (int j = 0; j < 2; ++j) {
                const char* pb = stg + 2 * SLOT
                               + (wn * 64 + ni * 16 + j * 8 + gid) * 48 + kb;
                bh[ni][j][0] = *(const uint32_t*)(pb);
                bh[ni][j][1] = *(const uint32_t*)(pb + 16);
                bl[ni][j][0] = *(const uint32_t*)(pb + SLOT);
                bl[ni][j][1] = *(const uint32_t*)(pb + SLOT + 16);
            }

#pragma unroll
        for (int mi = 0; mi < 2; ++mi)
#pragma unroll
            for (int ni = 0; ni < 4; ++ni) {
                mma16816(acc[mi][ni * 2],     ah[mi], bh[ni][0][0], bh[ni][0][1]);
                mma16816(acc[mi][ni * 2 + 1], ah[mi], bh[ni][1][0], bh[ni][1][1]);
                mma16816(acc[mi][ni * 2],     al[mi], bh[ni][0][0], bh[ni][0][1]);
                mma16816(acc[mi][ni * 2 + 1], al[mi], bh[ni][1][0], bh[ni][1][1]);
                mma16816(acc[mi][ni * 2],     ah[mi], bl[ni][0][0], bl[ni][0][1]);
                mma16816(acc[mi][ni * 2 + 1], ah[mi], bl[ni][1][0], bl[ni][1][1]);
            }
        __syncthreads();
    }

    // epilogue: c0/c1 at (row g, col 2t..2t+1), c2/c3 at (row g+8)
#pragma unroll
    for (int mi = 0; mi < 2; ++mi)
#pragma unroll
        for (int nf = 0; nf < 8; ++nf) {
            const int m = m0 + wm * 32 + mi * 16 + gid;
            const int n = n0 + wn * 64 + nf * 8 + tig * 2;
            p.store2(bz, m,     n, acc[mi][nf][0], acc[mi][nf][1]);
            p.store2(bz, m + 8, n, acc[mi][nf][2], acc[mi][nf][3]);
        }
}

// ---------------- fp32 -> bf16 hi/lo conversion ------------------------------
// Destination globals resolved in device code (sel); ONLY the input pointer
// (harness-owned) crosses the host/device boundary.
__global__ __launch_bounds__(256) void cvt_k(const float4* __restrict__ src,
                                             int n4, int sel)
{
    uint2* dh; uint2* dl;
    if (sel == 0)      { dh = (uint2*)g_xh;  dl = (uint2*)g_xl;  }
    else if (sel == 1) { dh = (uint2*)g_wih; dl = (uint2*)g_wil; }
    else               { dh = (uint2*)g_woh; dl = (uint2*)g_wol; }

    const int i = blockIdx.x * 256 + threadIdx.x;
    if (i >= n4) return;
    const float4 v = src[i];
    bf16 h0, l0, h1, l1, h2, l2, h3, l3;
    split(v.x, h0, l0); split(v.y, h1, l1);
    split(v.z, h2, l2); split(v.w, h3, l3);
    dh[i] = make_uint2(pk(h0, h1), pk(h2, h3));
    dl[i] = make_uint2(pk(l0, l1), pk(l2, l3));
}

// ---------------- softmax: fp32 scores -> bf16 hi/lo probabilities -----------
__global__ __launch_bounds__(256) void softmax_k()
{
    const size_t row = blockIdx.x;
    const float* p = g_sc + row * NS;
    const int t = threadIdx.x;

    float4 v = reinterpret_cast<const float4*>(p)[t];
    __shared__ float red[8];

    float mx = fmaxf(fmaxf(v.x, v.y), fmaxf(v.z, v.w));
#pragma unroll
    for (int o = 16; o > 0; o >>= 1)
        mx = fmaxf(mx, __shfl_xor_sync(0xffffffffu, mx, o));
    if ((t & 31) == 0) red[t >> 5] = mx;
    __syncthreads();
    float M = red[0];
#pragma unroll
    for (int w = 1; w < 8; ++w) M = fmaxf(M, red[w]);
    __syncthreads();

    v.x = expf(v.x - M); v.y = expf(v.y - M);
    v.z = expf(v.z - M); v.w = expf(v.w - M);
    float s = (v.x + v.y) + (v.z + v.w);
#pragma unroll
    for (int o = 16; o > 0; o >>= 1)
        s += __shfl_xor_sync(0xffffffffu, s, o);
    if ((t & 31) == 0) red[t >> 5] = s;
    __syncthreads();
    float S = red[0];
#pragma unroll
    for (int w = 1; w < 8; ++w) S += red[w];

    const float inv = 1.0f / S;
    v.x *= inv; v.y *= inv; v.z *= inv; v.w *= inv;

    bf16 h0, l0, h1, l1, h2, l2, h3, l3;
    split(v.x, h0, l0); split(v.y, h1, l1);
    split(v.z, h2, l2); split(v.w, h3, l3);
    reinterpret_cast<uint2*>(g_ph + row * NS)[t] = make_uint2(pk(h0, h1), pk(h2, h3));
    reinterpret_cast<uint2*>(g_pl + row * NS)[t] = make_uint2(pk(l0, l1), pk(l2, l3));
}

// ---------------- host --------------------------------------------------------
extern "C" void kernel_launch(void* const* d_in, const int* in_sizes, int n_in,
                              void* d_out, int out_size)
{
    (void)in_sizes; (void)n_in; (void)out_size;
    const float* x  = (const float*)d_in[0];
    const float* wi = (const float*)d_in[1];
    const float* bi = (const float*)d_in[2];
    const float* wo = (const float*)d_in[3];
    const float* bo = (const float*)d_in[4];
    float* out = (float*)d_out;

    // 0) split external fp32 operands into bf16 hi/lo (dest selected on device)
    cvt_k<<<(NB*NS*NE/4 + 255) / 256, 256>>>((const float4*)x,  NB*NS*NE/4, 0);
    cvt_k<<<(3*NE*NE/4  + 255) / 256, 256>>>((const float4*)wi, 3*NE*NE/4,  1);
    cvt_k<<<(NE*NE/4    + 255) / 256, 256>>>((const float4*)wo, NE*NE/4,    2);

    // 1) QKV projection (+bias, head scatter, V transposed)
    gemm_mma<PQkv><<<dim3(48, 32, 1), 256>>>(PQkv{bi}, NE);

    // 2) scores = (Q K^T) * scale
    gemm_mma<PScores><<<dim3(8, 8, NB * NH), 256>>>(PScores{}, ND);

    // 3) softmax -> P (hi/lo)
    softmax_k<<<NB * NH * NS, 256>>>();

    // 4) ctx = P V   (V pre-transposed to [d][s])
    gemm_mma<PCtx><<<dim3(1, 8, NB * NH), 256>>>(PCtx{}, NS);

    // 5) out = ctx W_out^T + bias
    gemm_mma<POut><<<dim3(16, 32, 1), 256>>>(POut{bo, out}, NE);
}

// round 7
// speedup vs baseline: 2.2953x; 1.1012x over previous
#include <cuda_runtime.h>
#include <cuda_bf16.h>
#include <math.h>
#include <stdint.h>

#define NB 4
#define NS 1024
#define NE 2048
#define NH 16
#define ND 128
#define ATTN_SCALE 0.08838834764831845f

typedef __nv_bfloat16 bf16;

// ---------------- scratch (device globals; referenced ONLY from device code) --
__device__ __align__(256) bf16 g_xh [(size_t)NB*NS*NE];
__device__ __align__(256) bf16 g_xl [(size_t)NB*NS*NE];
__device__ __align__(256) bf16 g_wih[(size_t)3*NE*NE];
__device__ __align__(256) bf16 g_wil[(size_t)3*NE*NE];
__device__ __align__(256) bf16 g_woh[(size_t)NE*NE];
__device__ __align__(256) bf16 g_wol[(size_t)NE*NE];
__device__ __align__(256) bf16 g_qh [(size_t)NB*NH*NS*ND];
__device__ __align__(256) bf16 g_ql [(size_t)NB*NH*NS*ND];
__device__ __align__(256) bf16 g_kh [(size_t)NB*NH*NS*ND];
__device__ __align__(256) bf16 g_kl [(size_t)NB*NH*NS*ND];
__device__ __align__(256) bf16 g_vTh[(size_t)NB*NH*ND*NS];   // [b,h,d,s]
__device__ __align__(256) bf16 g_vTl[(size_t)NB*NH*ND*NS];
__device__ __align__(256) bf16 g_ch [(size_t)NB*NS*NE];
__device__ __align__(256) bf16 g_cl [(size_t)NB*NS*NE];

// ---------------- PTX helpers ------------------------------------------------
__device__ __forceinline__ uint32_t smem_u32(const void* p) {
    uint32_t a;
    asm("{ .reg .u64 t; cvta.to.shared.u64 t, %1; cvt.u32.u64 %0, t; }" : "=r"(a) : "l"(p));
    return a;
}

#define CP16(dst, src) \
    asm volatile("cp.async.cg.shared.global [%0], [%1], 16;" :: "r"(dst), "l"(src) : "memory")
#define CP_COMMIT() asm volatile("cp.async.commit_group;" ::: "memory")
#define CP_WAIT1()  asm volatile("cp.async.wait_group 1;" ::: "memory")
#define CP_WAIT0()  asm volatile("cp.async.wait_group 0;" ::: "memory")

__device__ __forceinline__ void mma16816(float* d, const uint32_t* a, uint32_t b0, uint32_t b1) {
    asm volatile(
        "mma.sync.aligned.m16n8k16.row.col.f32.bf16.bf16.f32 "
        "{%0,%1,%2,%3}, {%4,%5,%6,%7}, {%8,%9}, {%0,%1,%2,%3};"
        : "+f"(d[0]), "+f"(d[1]), "+f"(d[2]), "+f"(d[3])
        : "r"(a[0]), "r"(a[1]), "r"(a[2]), "r"(a[3]), "r"(b0), "r"(b1));
}

__device__ __forceinline__ uint32_t pk(bf16 a, bf16 b) {
    return (uint32_t)__bfloat16_as_ushort(a) | ((uint32_t)__bfloat16_as_ushort(b) << 16);
}
__device__ __forceinline__ void split(float v, bf16& h, bf16& l) {
    h = __float2bfloat16(v);
    l = __float2bfloat16(v - __bfloat162float(h));
}

// ---------------- operand-source / epilogue param structs -------------------
struct PQkv {
    const float* bias;
    __device__ const bf16* ptr(int w, int) const {
        return w == 0 ? g_xh : w == 1 ? g_xl : w == 2 ? g_wih : g_wil;
    }
    __device__ __forceinline__ void store2(int, int m, int n, float v0, float v1) const {
        v0 += bias[n]; v1 += bias[n + 1];
        bf16 h0, l0, h1, l1;
        split(v0, h0, l0); split(v1, h1, l1);
        const int which = n >> 11;
        const int e = n & 2047, h = e >> 7, d = e & 127;
        const int b = m >> 10, s = m & 1023;
        if (which < 2) {
            bf16* dh = which == 0 ? g_qh : g_kh;
            bf16* dl = which == 0 ? g_ql : g_kl;
            const size_t off = ((size_t)((b * NH + h) * NS + s)) * ND + d;
            *(uint32_t*)(dh + off) = pk(h0, h1);
            *(uint32_t*)(dl + off) = pk(l0, l1);
        } else {
            const size_t off = ((size_t)((b * NH + h) * ND + d)) * NS + s;
            g_vTh[off]      = h0;  g_vTh[off + NS] = h1;
            g_vTl[off]      = l0;  g_vTl[off + NS] = l1;
        }
    }
};

struct POut {
    const float* bias;
    float* out;
    __device__ const bf16* ptr(int w, int) const {
        return w == 0 ? g_ch : w == 1 ? g_cl : w == 2 ? g_woh : g_wol;
    }
    __device__ __forceinline__ void store2(int, int m, int n, float v0, float v1) const {
        float2 o = make_float2(v0 + bias[n], v1 + bias[n + 1]);
        *(float2*)(out + (size_t)m * NE + n) = o;
    }
};

// ---------------- split-bf16 MMA GEMM (projections) --------------------------
#define SLOT   6144u
#define STAGE  24576u

template <class P>
__global__ __launch_bounds__(256) void gemm_mma(P p, int K)
{
    __shared__ __align__(1024) char smem[2 * STAGE];
    const uint32_t sb = smem_u32(smem);
    const int tid  = threadIdx.x;
    const int lane = tid & 31, wid = tid >> 5;
    const int wm = wid >> 1, wn = wid & 1;
    const int gid = lane >> 2, tig = lane & 3;
    const int bz = blockIdx.z;
    const int m0 = blockIdx.y * 128, n0 = blockIdx.x * 128;

    const bf16* ap[2] = { p.ptr(0, bz), p.ptr(1, bz) };
    const bf16* bp[2] = { p.ptr(2, bz), p.ptr(3, bz) };

    const int r = tid >> 1, cc = tid & 1;

    auto issue = [&](int st, int kt) {
        const uint32_t s = sb + (uint32_t)st * STAGE;
#pragma unroll
        for (int t = 0; t < 2; ++t)
            CP16(s + t * SLOT + (uint32_t)(r * 48 + cc * 16),
                 ap[t] + (size_t)(m0 + r) * K + kt + cc * 8);
#pragma unroll
        for (int t = 0; t < 2; ++t)
            CP16(s + (2 + t) * SLOT + (uint32_t)(r * 48 + cc * 16),
                 bp[t] + (size_t)(n0 + r) * K + kt + cc * 8);
    };

    float acc[2][8][4];
#pragma unroll
    for (int i = 0; i < 2; ++i)
#pragma unroll
        for (int j = 0; j < 8; ++j)
#pragma unroll
            for (int q = 0; q < 4; ++q) acc[i][j][q] = 0.0f;

    issue(0, 0);
    CP_COMMIT();

    const int NC = K >> 4;
    for (int c = 0; c < NC; ++c) {
        if (c + 1 < NC) { issue((c + 1) & 1, (c + 1) << 4); CP_COMMIT(); CP_WAIT1(); }
        else            { CP_WAIT0(); }
        __syncthreads();

        const char* stg = smem + (size_t)(c & 1) * STAGE;
        const int kb = tig * 4;

        uint32_t ah[2][4], al[2][4];
#pragma unroll
        for (int mi = 0; mi < 2; ++mi) {
            const char* pa = stg + (wm * 32 + mi * 16 + gid) * 48 + kb;
            ah[mi][0] = *(const uint32_t*)(pa);
            ah[mi][1] = *(const uint32_t*)(pa + 8 * 48);
            ah[mi][2] = *(const uint32_t*)(pa + 16);
            ah[mi][3] = *(const uint32_t*)(pa + 8 * 48 + 16);
            al[mi][0] = *(const uint32_t*)(pa + SLOT);
            al[mi][1] = *(const uint32_t*)(pa + SLOT + 8 * 48);
            al[mi][2] = *(const uint32_t*)(pa + SLOT + 16);
            al[mi][3] = *(const uint32_t*)(pa + SLOT + 8 * 48 + 16);
        }

        uint32_t bh[4][2][2], bl[4][2][2];
#pragma unroll
        for (int ni = 0; ni < 4; ++ni)
#pragma unroll
            for (int j = 0; j < 2; ++j) {
                const char* pb = stg + 2 * SLOT
                               + (wn * 64 + ni * 16 + j * 8 + gid) * 48 + kb;
                bh[ni][j][0] = *(const uint32_t*)(pb);
                bh[ni][j][1] = *(const uint32_t*)(pb + 16);
                bl[ni][j][0] = *(const uint32_t*)(pb + SLOT);
                bl[ni][j][1] = *(const uint32_t*)(pb + SLOT + 16);
            }

#pragma unroll
        for (int mi = 0; mi < 2; ++mi)
#pragma unroll
            for (int ni = 0; ni < 4; ++ni) {
                mma16816(acc[mi][ni * 2],     ah[mi], bh[ni][0][0], bh[ni][0][1]);
                mma16816(acc[mi][ni * 2 + 1], ah[mi], bh[ni][1][0], bh[ni][1][1]);
                mma16816(acc[mi][ni * 2],     al[mi], bh[ni][0][0], bh[ni][0][1]);
                mma16816(acc[mi][ni * 2 + 1], al[mi], bh[ni][1][0], bh[ni][1][1]);
                mma16816(acc[mi][ni * 2],     ah[mi], bl[ni][0][0], bl[ni][0][1]);
                mma16816(acc[mi][ni * 2 + 1], ah[mi], bl[ni][1][0], bl[ni][1][1]);
            }
        __syncthreads();
    }

#pragma unroll
    for (int mi = 0; mi < 2; ++mi)
#pragma unroll
        for (int nf = 0; nf < 8; ++nf) {
            const int m = m0 + wm * 32 + mi * 16 + gid;
            const int n = n0 + wn * 64 + nf * 8 + tig * 2;
            p.store2(bz, m,     n, acc[mi][nf][0], acc[mi][nf][1]);
            p.store2(bz, m + 8, n, acc[mi][nf][2], acc[mi][nf][3]);
        }
}

// ---------------- fused flash attention ---------------------------------------
// One CTA = 128 q-rows of one (b,h). 8 warps x 16 q-rows. Q hi/lo in registers.
// KV streamed in 64-row tiles, double-buffered dynamic smem.
// S = Qh·Kh + Ql·Kh + Qh·Kl ; online softmax (exp2 domain) ; O += Ph·Vh + Pl·Vh + Ph·Vl.
#define KH_OFF 0u
#define KL_OFF 17408u
#define VH_OFF 34816u
#define VL_OFF 53248u
#define FSTAGE 71680u
#define FSMEM  (2 * 71680)
#define SCL2   (ATTN_SCALE * 1.4426950408889634f)

__global__ __launch_bounds__(256, 1) void flash_attn()
{
    extern __shared__ __align__(1024) char fsm[];
    const uint32_t sb = smem_u32(fsm);
    const int tid  = threadIdx.x;
    const int lane = tid & 31, wid = tid >> 5;
    const int gid = lane >> 2, tig = lane & 3;
    const int bz = blockIdx.y;
    const int q0 = blockIdx.x * 128 + wid * 16 + gid;

    const bf16* Kh = g_kh  + (size_t)bz * NS * ND;
    const bf16* Kl = g_kl  + (size_t)bz * NS * ND;
    const bf16* Vh = g_vTh + (size_t)bz * ND * NS;
    const bf16* Vl = g_vTl + (size_t)bz * ND * NS;

    // Q fragments (persist in registers)
    uint32_t qh[8][4], ql[8][4];
    {
        const bf16* Qh = g_qh + ((size_t)bz * NS + q0) * ND;
        const bf16* Ql = g_ql + ((size_t)bz * NS + q0) * ND;
#pragma unroll
        for (int kc = 0; kc < 8; ++kc) {
            const int k0 = kc * 16 + tig * 2;
            qh[kc][0] = *(const uint32_t*)(Qh + k0);
            qh[kc][1] = *(const uint32_t*)(Qh + 8 * ND + k0);
            qh[kc][2] = *(const uint32_t*)(Qh + k0 + 8);
            qh[kc][3] = *(const uint32_t*)(Qh + 8 * ND + k0 + 8);
            ql[kc][0] = *(const uint32_t*)(Ql + k0);
            ql[kc][1] = *(const uint32_t*)(Ql + 8 * ND + k0);
            ql[kc][2] = *(const uint32_t*)(Ql + k0 + 8);
            ql[kc][3] = *(const uint32_t*)(Ql + 8 * ND + k0 + 8);
        }
    }

    auto issue = [&](int st, int kv0) {
        const uint32_t s = sb + (uint32_t)st * FSTAGE;
#pragma unroll
        for (int i = 0; i < 4; ++i) {
            const int idx = tid + i * 256;
            {   // K tile: 64 rows (s) x 128 d; pitch 272B
                const int r = idx >> 4, c = idx & 15;
                CP16(s + KH_OFF + (uint32_t)(r * 272 + c * 16),
                     Kh + (size_t)(kv0 + r) * ND + c * 8);
                CP16(s + KL_OFF + (uint32_t)(r * 272 + c * 16),
                     Kl + (size_t)(kv0 + r) * ND + c * 8);
            }
            {   // V tile: 128 rows (d) x 64 s; pitch 144B
                const int r = idx >> 3, c = idx & 7;
                CP16(s + VH_OFF + (uint32_t)(r * 144 + c * 16),
                     Vh + (size_t)r * NS + kv0 + c * 8);
                CP16(s + VL_OFF + (uint32_t)(r * 144 + c * 16),
                     Vl + (size_t)r * NS + kv0 + c * 8);
            }
        }
    };

    float oacc[16][4];
#pragma unroll
    for (int i = 0; i < 16; ++i)
#pragma unroll
        for (int q = 0; q < 4; ++q) oacc[i][q] = 0.0f;
    float m0 = -1e30f, m1 = -1e30f, l0 = 0.0f, l1 = 0.0f;

    issue(0, 0);
    CP_COMMIT();

    for (int t = 0; t < 16; ++t) {
        if (t + 1 < 16) { issue((t + 1) & 1, (t + 1) * 64); CP_COMMIT(); CP_WAIT1(); }
        else            { CP_WAIT0(); }
        __syncthreads();

        const char* stg = fsm + (size_t)(t & 1) * FSTAGE;

        // ---- S = Q·K^T (warp tile 16x64) ----
        float sacc[8][4];
#pragma unroll
        for (int nf = 0; nf < 8; ++nf)
#pragma unroll
            for (int q = 0; q < 4; ++q) sacc[nf][q] = 0.0f;

#pragma unroll
        for (int kc = 0; kc < 8; ++kc)
#pragma unroll
            for (int nf = 0; nf < 8; ++nf) {
                const char* pb = stg + KH_OFF + (nf * 8 + gid) * 272 + kc * 32 + tig * 4;
                const uint32_t bh0 = *(const uint32_t*)(pb);
                const uint32_t bh1 = *(const uint32_t*)(pb + 16);
                const uint32_t bl0 = *(const uint32_t*)(pb + (KL_OFF - KH_OFF));
                const uint32_t bl1 = *(const uint32_t*)(pb + (KL_OFF - KH_OFF) + 16);
                mma16816(sacc[nf], qh[kc], bh0, bh1);
                mma16816(sacc[nf], ql[kc], bh0, bh1);
                mma16816(sacc[nf], qh[kc], bl0, bl1);
            }

        // ---- online softmax (exp2 domain) ----
        float rm0 = -1e30f, rm1 = -1e30f;
#pragma unroll
        for (int nf = 0; nf < 8; ++nf) {
            sacc[nf][0] *= SCL2; sacc[nf][1] *= SCL2;
            sacc[nf][2] *= SCL2; sacc[nf][3] *= SCL2;
            rm0 = fmaxf(rm0, fmaxf(sacc[nf][0], sacc[nf][1]));
            rm1 = fmaxf(rm1, fmaxf(sacc[nf][2], sacc[nf][3]));
        }
        rm0 = fmaxf(rm0, __shfl_xor_sync(0xffffffffu, rm0, 1));
        rm0 = fmaxf(rm0, __shfl_xor_sync(0xffffffffu, rm0, 2));
        rm1 = fmaxf(rm1, __shfl_xor_sync(0xffffffffu, rm1, 1));
        rm1 = fmaxf(rm1, __shfl_xor_sync(0xffffffffu, rm1, 2));

        const float mn0 = fmaxf(m0, rm0), mn1 = fmaxf(m1, rm1);
        const float al0 = exp2f(m0 - mn0), al1 = exp2f(m1 - mn1);
        m0 = mn0; m1 = mn1;

        float sum0 = 0.0f, sum1 = 0.0f;
#pragma unroll
        for (int nf = 0; nf < 8; ++nf) {
            sacc[nf][0] = exp2f(sacc[nf][0] - m0);
            sacc[nf][1] = exp2f(sacc[nf][1] - m0);
            sacc[nf][2] = exp2f(sacc[nf][2] - m1);
            sacc[nf][3] = exp2f(sacc[nf][3] - m1);
            sum0 += sacc[nf][0] + sacc[nf][1];
            sum1 += sacc[nf][2] + sacc[nf][3];
        }
        sum0 += __shfl_xor_sync(0xffffffffu, sum0, 1);
        sum0 += __shfl_xor_sync(0xffffffffu, sum0, 2);
        sum1 += __shfl_xor_sync(0xffffffffu, sum1, 1);
        sum1 += __shfl_xor_sync(0xffffffffu, sum1, 2);
        l0 = l0 * al0 + sum0;
        l1 = l1 * al1 + sum1;

#pragma unroll
        for (int nf = 0; nf < 16; ++nf) {
            oacc[nf][0] *= al0; oacc[nf][1] *= al0;
            oacc[nf][2] *= al1; oacc[nf][3] *= al1;
        }

        // ---- O += P·V ----
#pragma unroll
        for (int kc = 0; kc < 4; ++kc) {
            uint32_t ph[4], pl[4];
            {
                bf16 a0, b0, a1, b1;
                split(sacc[2 * kc][0], a0, b0); split(sacc[2 * kc][1], a1, b1);
                ph[0] = pk(a0, a1); pl[0] = pk(b0, b1);
                split(sacc[2 * kc][2], a0, b0); split(sacc[2 * kc][3], a1, b1);
                ph[1] = pk(a0, a1); pl[1] = pk(b0, b1);
                split(sacc[2 * kc + 1][0], a0, b0); split(sacc[2 * kc + 1][1], a1, b1);
                ph[2] = pk(a0, a1); pl[2] = pk(b0, b1);
                split(sacc[2 * kc + 1][2], a0, b0); split(sacc[2 * kc + 1][3], a1, b1);
                ph[3] = pk(a0, a1); pl[3] = pk(b0, b1);
            }
#pragma unroll
            for (int nf = 0; nf < 16; ++nf) {
                const char* pb = stg + VH_OFF + (nf * 8 + gid) * 144 + kc * 32 + tig * 4;
                const uint32_t vb0 = *(const uint32_t*)(pb);
                const uint32_t vb1 = *(const uint32_t*)(pb + 16);
                const uint32_t vc0 = *(const uint32_t*)(pb + (VL_OFF - VH_OFF));
                const uint32_t vc1 = *(const uint32_t*)(pb + (VL_OFF - VH_OFF) + 16);
                mma16816(oacc[nf], ph, vb0, vb1);
                mma16816(oacc[nf], pl, vb0, vb1);
                mma16816(oacc[nf], ph, vc0, vc1);
            }
        }
        __syncthreads();
    }

    // ---- epilogue: normalize, split, store ctx hi/lo ----
    const float inv0 = 1.0f / l0, inv1 = 1.0f / l1;
    const int b = bz >> 4, h = bz & 15;
    const size_t base = ((size_t)(b * NS + q0)) * NE + h * ND;
#pragma unroll
    for (int nf = 0; nf < 16; ++nf) {
        const int d = nf * 8 + tig * 2;
        bf16 h0, lo0, h1, lo1;
        split(oacc[nf][0] * inv0, h0, lo0); split(oacc[nf][1] * inv0, h1, lo1);
        *(uint32_t*)(g_ch + base + d) = pk(h0, h1);
        *(uint32_t*)(g_cl + base + d) = pk(lo0, lo1);
        split(oacc[nf][2] * inv1, h0, lo0); split(oacc[nf][3] * inv1, h1, lo1);
        *(uint32_t*)(g_ch + base + 8 * NE + d) = pk(h0, h1);
        *(uint32_t*)(g_cl + base + 8 * NE + d) = pk(lo0, lo1);
    }
}

// ---------------- fp32 -> bf16 hi/lo conversion ------------------------------
__global__ __launch_bounds__(256) void cvt_k(const float4* __restrict__ src,
                                             int n4, int sel)
{
    uint2* dh; uint2* dl;
    if (sel == 0)      { dh = (uint2*)g_xh;  dl = (uint2*)g_xl;  }
    else if (sel == 1) { dh = (uint2*)g_wih; dl = (uint2*)g_wil; }
    else               { dh = (uint2*)g_woh; dl = (uint2*)g_wol; }

    const int i = blockIdx.x * 256 + threadIdx.x;
    if (i >= n4) return;
    const float4 v = src[i];
    bf16 h0, l0, h1, l1, h2, l2, h3, l3;
    split(v.x, h0, l0); split(v.y, h1, l1);
    split(v.z, h2, l2); split(v.w, h3, l3);
    dh[i] = make_uint2(pk(h0, h1), pk(h2, h3));
    dl[i] = make_uint2(pk(l0, l1), pk(l2, l3));
}

// ---------------- host --------------------------------------------------------
extern "C" void kernel_launch(void* const* d_in, const int* in_sizes, int n_in,
                              void* d_out, int out_size)
{
    (void)in_sizes; (void)n_in; (void)out_size;
    const float* x  = (const float*)d_in[0];
    const float* wi = (const float*)d_in[1];
    const float* bi = (const float*)d_in[2];
    const float* wo = (const float*)d_in[3];
    const float* bo = (const float*)d_in[4];
    float* out = (float*)d_out;

    cudaFuncSetAttribute(flash_attn, cudaFuncAttributeMaxDynamicSharedMemorySize, FSMEM);

    // 0) split external fp32 operands into bf16 hi/lo
    cvt_k<<<(NB*NS*NE/4 + 255) / 256, 256>>>((const float4*)x,  NB*NS*NE/4, 0);
    cvt_k<<<(3*NE*NE/4  + 255) / 256, 256>>>((const float4*)wi, 3*NE*NE/4,  1);
    cvt_k<<<(NE*NE/4    + 255) / 256, 256>>>((const float4*)wo, NE*NE/4,    2);

    // 1) QKV projection (+bias, head scatter, V transposed)
    gemm_mma<PQkv><<<dim3(48, 32, 1), 256>>>(PQkv{bi}, NE);

    // 2-4) fused attention: scores + softmax + P·V
    flash_attn<<<dim3(NS / 128, NB * NH), 256, FSMEM>>>();

    // 5) out = ctx W_out^T + bias
    gemm_mma<POut><<<dim3(16, 32, 1), 256>>>(POut{bo, out}, NE);
}

// round 8
// speedup vs baseline: 2.3637x; 1.0298x over previous
#include <cuda_runtime.h>
#include <cuda_bf16.h>
#include <math.h>
#include <stdint.h>

#define NB 4
#define NS 1024
#define NE 2048
#define NH 16
#define ND 128
#define ATTN_SCALE 0.08838834764831845f

typedef __nv_bfloat16 bf16;

// ---------------- scratch (device globals; referenced ONLY from device code) --
__device__ __align__(256) bf16 g_xh [(size_t)NB*NS*NE];
__device__ __align__(256) bf16 g_xl [(size_t)NB*NS*NE];
__device__ __align__(256) bf16 g_wih[(size_t)3*NE*NE];
__device__ __align__(256) bf16 g_wil[(size_t)3*NE*NE];
__device__ __align__(256) bf16 g_woh[(size_t)NE*NE];
__device__ __align__(256) bf16 g_wol[(size_t)NE*NE];
__device__ __align__(256) bf16 g_qh [(size_t)NB*NH*NS*ND];
__device__ __align__(256) bf16 g_ql [(size_t)NB*NH*NS*ND];
__device__ __align__(256) bf16 g_kh [(size_t)NB*NH*NS*ND];
__device__ __align__(256) bf16 g_kl [(size_t)NB*NH*NS*ND];
__device__ __align__(256) bf16 g_vTh[(size_t)NB*NH*ND*NS];   // [b,h,d,s]
__device__ __align__(256) bf16 g_vTl[(size_t)NB*NH*ND*NS];
__device__ __align__(256) bf16 g_ch [(size_t)NB*NS*NE];
__device__ __align__(256) bf16 g_cl [(size_t)NB*NS*NE];

// ---------------- PTX helpers ------------------------------------------------
__device__ __forceinline__ uint32_t smem_u32(const void* p) {
    uint32_t a;
    asm("{ .reg .u64 t; cvta.to.shared.u64 t, %1; cvt.u32.u64 %0, t; }" : "=r"(a) : "l"(p));
    return a;
}

#define CP16(dst, src) \
    asm volatile("cp.async.cg.shared.global [%0], [%1], 16;" :: "r"(dst), "l"(src) : "memory")
#define CP_COMMIT() asm volatile("cp.async.commit_group;" ::: "memory")
#define CP_WAIT1()  asm volatile("cp.async.wait_group 1;" ::: "memory")
#define CP_WAIT0()  asm volatile("cp.async.wait_group 0;" ::: "memory")

__device__ __forceinline__ void ldsm4(uint32_t* r, uint32_t a) {
    asm volatile("ldmatrix.sync.aligned.m8n8.x4.shared.b16 {%0,%1,%2,%3}, [%4];"
                 : "=r"(r[0]), "=r"(r[1]), "=r"(r[2]), "=r"(r[3]) : "r"(a));
}
__device__ __forceinline__ void mma16816(float* d, const uint32_t* a, uint32_t b0, uint32_t b1) {
    asm volatile(
        "mma.sync.aligned.m16n8k16.row.col.f32.bf16.bf16.f32 "
        "{%0,%1,%2,%3}, {%4,%5,%6,%7}, {%8,%9}, {%0,%1,%2,%3};"
        : "+f"(d[0]), "+f"(d[1]), "+f"(d[2]), "+f"(d[3])
        : "r"(a[0]), "r"(a[1]), "r"(a[2]), "r"(a[3]), "r"(b0), "r"(b1));
}

__device__ __forceinline__ uint32_t pk(bf16 a, bf16 b) {
    return (uint32_t)__bfloat16_as_ushort(a) | ((uint32_t)__bfloat16_as_ushort(b) << 16);
}
__device__ __forceinline__ void split(float v, bf16& h, bf16& l) {
    h = __float2bfloat16(v);
    l = __float2bfloat16(v - __bfloat162float(h));
}

// ---------------- operand-source / epilogue param structs -------------------
struct PQkv {
    const float* bias;
    __device__ const bf16* ptr(int w, int) const {
        return w == 0 ? g_xh : w == 1 ? g_xl : w == 2 ? g_wih : g_wil;
    }
    __device__ __forceinline__ void store2(int, int m, int n, float v0, float v1) const {
        v0 += bias[n]; v1 += bias[n + 1];
        bf16 h0, l0, h1, l1;
        split(v0, h0, l0); split(v1, h1, l1);
        const int which = n >> 11;
        const int e = n & 2047, h = e >> 7, d = e & 127;
        const int b = m >> 10, s = m & 1023;
        if (which < 2) {
            bf16* dh = which == 0 ? g_qh : g_kh;
            bf16* dl = which == 0 ? g_ql : g_kl;
            const size_t off = ((size_t)((b * NH + h) * NS + s)) * ND + d;
            *(uint32_t*)(dh + off) = pk(h0, h1);
            *(uint32_t*)(dl + off) = pk(l0, l1);
        } else {
            const size_t off = ((size_t)((b * NH + h) * ND + d)) * NS + s;
            g_vTh[off]      = h0;  g_vTh[off + NS] = h1;
            g_vTl[off]      = l0;  g_vTl[off + NS] = l1;
        }
    }
};

struct POut {
    const float* bias;
    float* out;
    __device__ const bf16* ptr(int w, int) const {
        return w == 0 ? g_ch : w == 1 ? g_cl : w == 2 ? g_woh : g_wol;
    }
    __device__ __forceinline__ void store2(int, int m, int n, float v0, float v1) const {
        float2 o = make_float2(v0 + bias[n], v1 + bias[n + 1]);
        *(float2*)(out + (size_t)m * NE + n) = o;
    }
};

// ---------------- split-bf16 MMA GEMM (projections) --------------------------
// C[128,128] = Ah·Bh^T + Al·Bh^T + Ah·Bl^T, fp32 accum. BK=32.
// Tile: 128 rows x 64B data + 16B pad = 80B pitch (conflict-free for cp.async
// stores and ldmatrix row fetches). 4 tiles/stage = 40KB; double-buffered
// 80KB dynamic smem. Fragments via ldmatrix.x4.
#define SLOT2  10240u
#define STG2   40960u
#define GSMEM  (2 * 40960)

template <class P>
__global__ __launch_bounds__(256) void gemm_mma(P p, int K)
{
    extern __shared__ __align__(1024) char gsm[];
    const uint32_t sb = smem_u32(gsm);
    const int tid  = threadIdx.x;
    const int lane = tid & 31, wid = tid >> 5;
    const int wm = wid >> 1, wn = wid & 1;       // 4x2 warp grid, warp tile 32x64
    const int gid = lane >> 2, tig = lane & 3;
    const int bz = blockIdx.z;
    const int m0 = blockIdx.y * 128, n0 = blockIdx.x * 128;

    const bf16* ap[2] = { p.ptr(0, bz), p.ptr(1, bz) };
    const bf16* bp[2] = { p.ptr(2, bz), p.ptr(3, bz) };

    // cp.async: per tile 128 rows x 4 16B-chunks = 512; 2 per thread per tile
    auto issue = [&](int st, int kt) {
        const uint32_t s = sb + (uint32_t)st * STG2;
#pragma unroll
        for (int i = 0; i < 2; ++i) {
            const int idx = tid + i * 256;
            const int r = idx >> 2, c = idx & 3;
            const uint32_t d = (uint32_t)(r * 80 + c * 16);
            const size_t  o = (size_t)r * K + kt + c * 8;
            CP16(s + d,             ap[0] + (size_t)m0 * K + o);
            CP16(s + SLOT2 + d,     ap[1] + (size_t)m0 * K + o);
            CP16(s + 2 * SLOT2 + d, bp[0] + (size_t)n0 * K + o);
            CP16(s + 3 * SLOT2 + d, bp[1] + (size_t)n0 * K + o);
        }
    };

    // ldmatrix address offsets (stage-relative), fixed per thread
    uint32_t a_off[2], b_off[4];
#pragma unroll
    for (int mi = 0; mi < 2; ++mi)
        a_off[mi] = (uint32_t)((wm * 32 + mi * 16 + (lane & 15)) * 80 + (lane >> 4) * 16);
#pragma unroll
    for (int nb = 0; nb < 4; ++nb) {
        const int rw = wn * 64 + nb * 16 + (lane & 7) + ((lane >> 4) & 1) * 8;
        b_off[nb] = (uint32_t)(rw * 80 + ((lane >> 3) & 1) * 16);
    }

    float acc[2][8][4];
#pragma unroll
    for (int i = 0; i < 2; ++i)
#pragma unroll
        for (int j = 0; j < 8; ++j)
#pragma unroll
            for (int q = 0; q < 4; ++q) acc[i][j][q] = 0.0f;

    issue(0, 0);
    CP_COMMIT();

    const int NC = K >> 5;
    for (int c = 0; c < NC; ++c) {
        if (c + 1 < NC) { issue((c + 1) & 1, (c + 1) << 5); CP_COMMIT(); CP_WAIT1(); }
        else            { CP_WAIT0(); }
        __syncthreads();

        const uint32_t s = sb + (uint32_t)(c & 1) * STG2;
#pragma unroll
        for (int kh = 0; kh < 2; ++kh) {
            const uint32_t ka = kh * 32;     // 16 k-elements = 32 bytes

            uint32_t ah[2][4], al[2][4];
#pragma unroll
            for (int mi = 0; mi < 2; ++mi) {
                ldsm4(ah[mi], s + a_off[mi] + ka);
                ldsm4(al[mi], s + SLOT2 + a_off[mi] + ka);
            }
#pragma unroll
            for (int nb = 0; nb < 4; ++nb) {
                uint32_t bh[4], bl[4];
                ldsm4(bh, s + 2 * SLOT2 + b_off[nb] + ka);
                ldsm4(bl, s + 3 * SLOT2 + b_off[nb] + ka);
#pragma unroll
                for (int mi = 0; mi < 2; ++mi) {
                    mma16816(acc[mi][nb * 2],     ah[mi], bh[0], bh[1]);
                    mma16816(acc[mi][nb * 2 + 1], ah[mi], bh[2], bh[3]);
                    mma16816(acc[mi][nb * 2],     al[mi], bh[0], bh[1]);
                    mma16816(acc[mi][nb * 2 + 1], al[mi], bh[2], bh[3]);
                    mma16816(acc[mi][nb * 2],     ah[mi], bl[0], bl[1]);
                    mma16816(acc[mi][nb * 2 + 1], ah[mi], bl[2], bl[3]);
                }
            }
        }
        __syncthreads();
    }

#pragma unroll
    for (int mi = 0; mi < 2; ++mi)
#pragma unroll
        for (int nf = 0; nf < 8; ++nf) {
            const int m = m0 + wm * 32 + mi * 16 + gid;
            const int n = n0 + wn * 64 + nf * 8 + tig * 2;
            p.store2(bz, m,     n, acc[mi][nf][0], acc[mi][nf][1]);
            p.store2(bz, m + 8, n, acc[mi][nf][2], acc[mi][nf][3]);
        }
}

// ---------------- fused flash attention (unchanged from R7) -------------------
#define KH_OFF 0u
#define KL_OFF 17408u
#define VH_OFF 34816u
#define VL_OFF 53248u
#define FSTAGE 71680u
#define FSMEM  (2 * 71680)
#define SCL2   (ATTN_SCALE * 1.4426950408889634f)

__global__ __launch_bounds__(256, 1) void flash_attn()
{
    extern __shared__ __align__(1024) char fsm[];
    const uint32_t sb = smem_u32(fsm);
    const int tid  = threadIdx.x;
    const int lane = tid & 31, wid = tid >> 5;
    const int gid = lane >> 2, tig = lane & 3;
    const int bz = blockIdx.y;
    const int q0 = blockIdx.x * 128 + wid * 16 + gid;

    const bf16* Kh = g_kh  + (size_t)bz * NS * ND;
    const bf16* Kl = g_kl  + (size_t)bz * NS * ND;
    const bf16* Vh = g_vTh + (size_t)bz * ND * NS;
    const bf16* Vl = g_vTl + (size_t)bz * ND * NS;

    uint32_t qh[8][4], ql[8][4];
    {
        const bf16* Qh = g_qh + ((size_t)bz * NS + q0) * ND;
        const bf16* Ql = g_ql + ((size_t)bz * NS + q0) * ND;
#pragma unroll
        for (int kc = 0; kc < 8; ++kc) {
            const int k0 = kc * 16 + tig * 2;
            qh[kc][0] = *(const uint32_t*)(Qh + k0);
            qh[kc][1] = *(const uint32_t*)(Qh + 8 * ND + k0);
            qh[kc][2] = *(const uint32_t*)(Qh + k0 + 8);
            qh[kc][3] = *(const uint32_t*)(Qh + 8 * ND + k0 + 8);
            ql[kc][0] = *(const uint32_t*)(Ql + k0);
            ql[kc][1] = *(const uint32_t*)(Ql + 8 * ND + k0);
            ql[kc][2] = *(const uint32_t*)(Ql + k0 + 8);
            ql[kc][3] = *(const uint32_t*)(Ql + 8 * ND + k0 + 8);
        }
    }

    auto issue = [&](int st, int kv0) {
        const uint32_t s = sb + (uint32_t)st * FSTAGE;
#pragma unroll
        for (int i = 0; i < 4; ++i) {
            const int idx = tid + i * 256;
            {
                const int r = idx >> 4, c = idx & 15;
                CP16(s + KH_OFF + (uint32_t)(r * 272 + c * 16),
                     Kh + (size_t)(kv0 + r) * ND + c * 8);
                CP16(s + KL_OFF + (uint32_t)(r * 272 + c * 16),
                     Kl + (size_t)(kv0 + r) * ND + c * 8);
            }
            {
                const int r = idx >> 3, c = idx & 7;
                CP16(s + VH_OFF + (uint32_t)(r * 144 + c * 16),
                     Vh + (size_t)r * NS + kv0 + c * 8);
                CP16(s + VL_OFF + (uint32_t)(r * 144 + c * 16),
                     Vl + (size_t)r * NS + kv0 + c * 8);
            }
        }
    };

    float oacc[16][4];
#pragma unroll
    for (int i = 0; i < 16; ++i)
#pragma unroll
        for (int q = 0; q < 4; ++q) oacc[i][q] = 0.0f;
    float m0 = -1e30f, m1 = -1e30f, l0 = 0.0f, l1 = 0.0f;

    issue(0, 0);
    CP_COMMIT();

    for (int t = 0; t < 16; ++t) {
        if (t + 1 < 16) { issue((t + 1) & 1, (t + 1) * 64); CP_COMMIT(); CP_WAIT1(); }
        else            { CP_WAIT0(); }
        __syncthreads();

        const char* stg = fsm + (size_t)(t & 1) * FSTAGE;

        float sacc[8][4];
#pragma unroll
        for (int nf = 0; nf < 8; ++nf)
#pragma unroll
            for (int q = 0; q < 4; ++q) sacc[nf][q] = 0.0f;

#pragma unroll
        for (int kc = 0; kc < 8; ++kc)
#pragma unroll
            for (int nf = 0; nf < 8; ++nf) {
                const char* pb = stg + KH_OFF + (nf * 8 + gid) * 272 + kc * 32 + tig * 4;
                const uint32_t bh0 = *(const uint32_t*)(pb);
                const uint32_t bh1 = *(const uint32_t*)(pb + 16);
                const uint32_t bl0 = *(const uint32_t*)(pb + (KL_OFF - KH_OFF));
                const uint32_t bl1 = *(const uint32_t*)(pb + (KL_OFF - KH_OFF) + 16);
                mma16816(sacc[nf], qh[kc], bh0, bh1);
                mma16816(sacc[nf], ql[kc], bh0, bh1);
                mma16816(sacc[nf], qh[kc], bl0, bl1);
            }

        float rm0 = -1e30f, rm1 = -1e30f;
#pragma unroll
        for (int nf = 0; nf < 8; ++nf) {
            sacc[nf][0] *= SCL2; sacc[nf][1] *= SCL2;
            sacc[nf][2] *= SCL2; sacc[nf][3] *= SCL2;
            rm0 = fmaxf(rm0, fmaxf(sacc[nf][0], sacc[nf][1]));
            rm1 = fmaxf(rm1, fmaxf(sacc[nf][2], sacc[nf][3]));
        }
        rm0 = fmaxf(rm0, __shfl_xor_sync(0xffffffffu, rm0, 1));
        rm0 = fmaxf(rm0, __shfl_xor_sync(0xffffffffu, rm0, 2));
        rm1 = fmaxf(rm1, __shfl_xor_sync(0xffffffffu, rm1, 1));
        rm1 = fmaxf(rm1, __shfl_xor_sync(0xffffffffu, rm1, 2));

        const float mn0 = fmaxf(m0, rm0), mn1 = fmaxf(m1, rm1);
        const float al0 = exp2f(m0 - mn0), al1 = exp2f(m1 - mn1);
        m0 = mn0; m1 = mn1;

        float sum0 = 0.0f, sum1 = 0.0f;
#pragma unroll
        for (int nf = 0; nf < 8; ++nf) {
            sacc[nf][0] = exp2f(sacc[nf][0] - m0);
            sacc[nf][1] = exp2f(sacc[nf][1] - m0);
            sacc[nf][2] = exp2f(sacc[nf][2] - m1);
            sacc[nf][3] = exp2f(sacc[nf][3] - m1);
            sum0 += sacc[nf][0] + sacc[nf][1];
            sum1 += sacc[nf][2] + sacc[nf][3];
        }
        sum0 += __shfl_xor_sync(0xffffffffu, sum0, 1);
        sum0 += __shfl_xor_sync(0xffffffffu, sum0, 2);
        sum1 += __shfl_xor_sync(0xffffffffu, sum1, 1);
        sum1 += __shfl_xor_sync(0xffffffffu, sum1, 2);
        l0 = l0 * al0 + sum0;
        l1 = l1 * al1 + sum1;

#pragma unroll
        for (int nf = 0; nf < 16; ++nf) {
            oacc[nf][0] *= al0; oacc[nf][1] *= al0;
            oacc[nf][2] *= al1; oacc[nf][3] *= al1;
        }

#pragma unroll
        for (int kc = 0; kc < 4; ++kc) {
            uint32_t ph[4], pl[4];
            {
                bf16 a0, b0, a1, b1;
                split(sacc[2 * kc][0], a0, b0); split(sacc[2 * kc][1], a1, b1);
                ph[0] = pk(a0, a1); pl[0] = pk(b0, b1);
                split(sacc[2 * kc][2], a0, b0); split(sacc[2 * kc][3], a1, b1);
                ph[1] = pk(a0, a1); pl[1] = pk(b0, b1);
                split(sacc[2 * kc + 1][0], a0, b0); split(sacc[2 * kc + 1][1], a1, b1);
                ph[2] = pk(a0, a1); pl[2] = pk(b0, b1);
                split(sacc[2 * kc + 1][2], a0, b0); split(sacc[2 * kc + 1][3], a1, b1);
                ph[3] = pk(a0, a1); pl[3] = pk(b0, b1);
            }
#pragma unroll
            for (int nf = 0; nf < 16; ++nf) {
                const char* pb = stg + VH_OFF + (nf * 8 + gid) * 144 + kc * 32 + tig * 4;
                const uint32_t vb0 = *(const uint32_t*)(pb);
                const uint32_t vb1 = *(const uint32_t*)(pb + 16);
                const uint32_t vc0 = *(const uint32_t*)(pb + (VL_OFF - VH_OFF));
                const uint32_t vc1 = *(const uint32_t*)(pb + (VL_OFF - VH_OFF) + 16);
                mma16816(oacc[nf], ph, vb0, vb1);
                mma16816(oacc[nf], pl, vb0, vb1);
                mma16816(oacc[nf], ph, vc0, vc1);
            }
        }
        __syncthreads();
    }

    const float inv0 = 1.0f / l0, inv1 = 1.0f / l1;
    const int b = bz >> 4, h = bz & 15;
    const size_t base = ((size_t)(b * NS + q0)) * NE + h * ND;
#pragma unroll
    for (int nf = 0; nf < 16; ++nf) {
        const int d = nf * 8 + tig * 2;
        bf16 h0, lo0, h1, lo1;
        split(oacc[nf][0] * inv0, h0, lo0); split(oacc[nf][1] * inv0, h1, lo1);
        *(uint32_t*)(g_ch + base + d) = pk(h0, h1);
        *(uint32_t*)(g_cl + base + d) = pk(lo0, lo1);
        split(oacc[nf][2] * inv1, h0, lo0); split(oacc[nf][3] * inv1, h1, lo1);
        *(uint32_t*)(g_ch + base + 8 * NE + d) = pk(h0, h1);
        *(uint32_t*)(g_cl + base + 8 * NE + d) = pk(lo0, lo1);
    }
}

// ---------------- fp32 -> bf16 hi/lo conversion ------------------------------
__global__ __launch_bounds__(256) void cvt_k(const float4* __restrict__ src,
                                             int n4, int sel)
{
    uint2* dh; uint2* dl;
    if (sel == 0)      { dh = (uint2*)g_xh;  dl = (uint2*)g_xl;  }
    else if (sel == 1) { dh = (uint2*)g_wih; dl = (uint2*)g_wil; }
    else               { dh = (uint2*)g_woh; dl = (uint2*)g_wol; }

    const int i = blockIdx.x * 256 + threadIdx.x;
    if (i >= n4) return;
    const float4 v = src[i];
    bf16 h0, l0, h1, l1, h2, l2, h3, l3;
    split(v.x, h0, l0); split(v.y, h1, l1);
    split(v.z, h2, l2); split(v.w, h3, l3);
    dh[i] = make_uint2(pk(h0, h1), pk(h2, h3));
    dl[i] = make_uint2(pk(l0, l1), pk(l2, l3));
}

// ---------------- host --------------------------------------------------------
extern "C" void kernel_launch(void* const* d_in, const int* in_sizes, int n_in,
                              void* d_out, int out_size)
{
    (void)in_sizes; (void)n_in; (void)out_size;
    const float* x  = (const float*)d_in[0];
    const float* wi = (const float*)d_in[1];
    const float* bi = (const float*)d_in[2];
    const float* wo = (const float*)d_in[3];
    const float* bo = (const float*)d_in[4];
    float* out = (float*)d_out;

    cudaFuncSetAttribute(gemm_mma<PQkv>, cudaFuncAttributeMaxDynamicSharedMemorySize, GSMEM);
    cudaFuncSetAttribute(gemm_mma<POut>, cudaFuncAttributeMaxDynamicSharedMemorySize, GSMEM);
    cudaFuncSetAttribute(flash_attn,     cudaFuncAttributeMaxDynamicSharedMemorySize, FSMEM);

    // 0) split external fp32 operands into bf16 hi/lo
    cvt_k<<<(NB*NS*NE/4 + 255) / 256, 256>>>((const float4*)x,  NB*NS*NE/4, 0);
    cvt_k<<<(3*NE*NE/4  + 255) / 256, 256>>>((const float4*)wi, 3*NE*NE/4,  1);
    cvt_k<<<(NE*NE/4    + 255) / 256, 256>>>((const float4*)wo, NE*NE/4,    2);

    // 1) QKV projection (+bias, head scatter, V transposed)
    gemm_mma<PQkv><<<dim3(48, 32, 1), 256, GSMEM>>>(PQkv{bi}, NE);

    // 2-4) fused attention: scores + softmax + P·V
    flash_attn<<<dim3(NS / 128, NB * NH), 256, FSMEM>>>();

    // 5) out = ctx W_out^T + bias
    gemm_mma<POut><<<dim3(16, 32, 1), 256, GSMEM>>>(POut{bo, out}, NE);
}

// round 9
// speedup vs baseline: 2.7450x; 1.1613x over previous
#include <cuda_runtime.h>
#include <cuda_bf16.h>
#include <math.h>
#include <stdint.h>

#define NB 4
#define NS 1024
#define NE 2048
#define NH 16
#define ND 128
#define ATTN_SCALE 0.08838834764831845f

typedef __nv_bfloat16 bf16;

// ---------------- scratch (device globals; referenced ONLY from device code) --
__device__ __align__(256) bf16 g_xh [(size_t)NB*NS*NE];
__device__ __align__(256) bf16 g_xl [(size_t)NB*NS*NE];
__device__ __align__(256) bf16 g_wih[(size_t)3*NE*NE];
__device__ __align__(256) bf16 g_wil[(size_t)3*NE*NE];
__device__ __align__(256) bf16 g_woh[(size_t)NE*NE];
__device__ __align__(256) bf16 g_wol[(size_t)NE*NE];
__device__ __align__(256) bf16 g_qh [(size_t)NB*NH*NS*ND];
__device__ __align__(256) bf16 g_ql [(size_t)NB*NH*NS*ND];
__device__ __align__(256) bf16 g_kh [(size_t)NB*NH*NS*ND];
__device__ __align__(256) bf16 g_kl [(size_t)NB*NH*NS*ND];
__device__ __align__(256) bf16 g_vTh[(size_t)NB*NH*ND*NS];   // [b,h,d,s]
__device__ __align__(256) bf16 g_vTl[(size_t)NB*NH*ND*NS];
__device__ __align__(256) bf16 g_ch [(size_t)NB*NS*NE];
__device__ __align__(256) bf16 g_cl [(size_t)NB*NS*NE];

// ---------------- PTX helpers ------------------------------------------------
__device__ __forceinline__ uint32_t smem_u32(const void* p) {
    uint32_t a;
    asm("{ .reg .u64 t; cvta.to.shared.u64 t, %1; cvt.u32.u64 %0, t; }" : "=r"(a) : "l"(p));
    return a;
}

#define CP16(dst, src) \
    asm volatile("cp.async.cg.shared.global [%0], [%1], 16;" :: "r"(dst), "l"(src) : "memory")
#define CP_COMMIT() asm volatile("cp.async.commit_group;" ::: "memory")
#define CP_WAIT1()  asm volatile("cp.async.wait_group 1;" ::: "memory")
#define CP_WAIT0()  asm volatile("cp.async.wait_group 0;" ::: "memory")

__device__ __forceinline__ void ldsm4(uint32_t* r, uint32_t a) {
    asm volatile("ldmatrix.sync.aligned.m8n8.x4.shared.b16 {%0,%1,%2,%3}, [%4];"
                 : "=r"(r[0]), "=r"(r[1]), "=r"(r[2]), "=r"(r[3]) : "r"(a));
}
__device__ __forceinline__ void mma16816(float* d, const uint32_t* a, uint32_t b0, uint32_t b1) {
    asm volatile(
        "mma.sync.aligned.m16n8k16.row.col.f32.bf16.bf16.f32 "
        "{%0,%1,%2,%3}, {%4,%5,%6,%7}, {%8,%9}, {%0,%1,%2,%3};"
        : "+f"(d[0]), "+f"(d[1]), "+f"(d[2]), "+f"(d[3])
        : "r"(a[0]), "r"(a[1]), "r"(a[2]), "r"(a[3]), "r"(b0), "r"(b1));
}

__device__ __forceinline__ uint32_t pk(bf16 a, bf16 b) {
    return (uint32_t)__bfloat16_as_ushort(a) | ((uint32_t)__bfloat16_as_ushort(b) << 16);
}
__device__ __forceinline__ void split(float v, bf16& h, bf16& l) {
    h = __float2bfloat16(v);
    l = __float2bfloat16(v - __bfloat162float(h));
}

// ---------------- operand-source / epilogue param structs -------------------
struct PQkv {
    const float* bias;
    __device__ const bf16* ptr(int w, int) const {
        return w == 0 ? g_xh : w == 1 ? g_xl : w == 2 ? g_wih : g_wil;
    }
    __device__ __forceinline__ void store2(int, int m, int n, float v0, float v1) const {
        v0 += bias[n]; v1 += bias[n + 1];
        bf16 h0, l0, h1, l1;
        split(v0, h0, l0); split(v1, h1, l1);
        const int which = n >> 11;
        const int e = n & 2047, h = e >> 7, d = e & 127;
        const int b = m >> 10, s = m & 1023;
        if (which < 2) {
            bf16* dh = which == 0 ? g_qh : g_kh;
            bf16* dl = which == 0 ? g_ql : g_kl;
            const size_t off = ((size_t)((b * NH + h) * NS + s)) * ND + d;
            *(uint32_t*)(dh + off) = pk(h0, h1);
            *(uint32_t*)(dl + off) = pk(l0, l1);
        } else {
            const size_t off = ((size_t)((b * NH + h) * ND + d)) * NS + s;
            g_vTh[off]      = h0;  g_vTh[off + NS] = h1;
            g_vTl[off]      = l0;  g_vTl[off + NS] = l1;
        }
    }
};

struct POut {
    const float* bias;
    float* out;
    __device__ const bf16* ptr(int w, int) const {
        return w == 0 ? g_ch : w == 1 ? g_cl : w == 2 ? g_woh : g_wol;
    }
    __device__ __forceinline__ void store2(int, int m, int n, float v0, float v1) const {
        float2 o = make_float2(v0 + bias[n], v1 + bias[n + 1]);
        *(float2*)(out + (size_t)m * NE + n) = o;
    }
};

// ---------------- split-bf16 MMA GEMM (projections) --------------------------
// C[128,128] = Ah·Bh^T + Al·Bh^T + Ah·Bl^T, fp32 accum. BK=32.
// Tile: 128 rows x 64B data + 16B pad = 80B pitch. 4 tiles/stage = 40KB;
// double-buffered 80KB dynamic smem. Fragments via ldmatrix.x4.
// __launch_bounds__(256, 2): cap regs at 128 so 2 CTAs co-reside per SM
// (R8 regression: 134 regs -> 1 CTA/SM -> barrier stalls uncovered).
#define SLOT2  10240u
#define STG2   40960u
#define GSMEM  (2 * 40960)

template <class P>
__global__ __launch_bounds__(256, 2) void gemm_mma(P p, int K)
{
    extern __shared__ __align__(1024) char gsm[];
    const uint32_t sb = smem_u32(gsm);
    const int tid  = threadIdx.x;
    const int lane = tid & 31, wid = tid >> 5;
    const int wm = wid >> 1, wn = wid & 1;       // 4x2 warp grid, warp tile 32x64
    const int gid = lane >> 2, tig = lane & 3;
    const int bz = blockIdx.z;
    const int m0 = blockIdx.y * 128, n0 = blockIdx.x * 128;

    const bf16* ap[2] = { p.ptr(0, bz), p.ptr(1, bz) };
    const bf16* bp[2] = { p.ptr(2, bz), p.ptr(3, bz) };

    auto issue = [&](int st, int kt) {
        const uint32_t s = sb + (uint32_t)st * STG2;
#pragma unroll
        for (int i = 0; i < 2; ++i) {
            const int idx = tid + i * 256;
            const int r = idx >> 2, c = idx & 3;
            const uint32_t d = (uint32_t)(r * 80 + c * 16);
            const size_t  o = (size_t)r * K + kt + c * 8;
            CP16(s + d,             ap[0] + (size_t)m0 * K + o);
            CP16(s + SLOT2 + d,     ap[1] + (size_t)m0 * K + o);
            CP16(s + 2 * SLOT2 + d, bp[0] + (size_t)n0 * K + o);
            CP16(s + 3 * SLOT2 + d, bp[1] + (size_t)n0 * K + o);
        }
    };

    // ldmatrix address offsets (stage-relative), fixed per thread
    uint32_t a_off[2], b_off[4];
#pragma unroll
    for (int mi = 0; mi < 2; ++mi)
        a_off[mi] = (uint32_t)((wm * 32 + mi * 16 + (lane & 15)) * 80 + (lane >> 4) * 16);
#pragma unroll
    for (int nb = 0; nb < 4; ++nb) {
        const int rw = wn * 64 + nb * 16 + (lane & 7) + ((lane >> 4) & 1) * 8;
        b_off[nb] = (uint32_t)(rw * 80 + ((lane >> 3) & 1) * 16);
    }

    float acc[2][8][4];
#pragma unroll
    for (int i = 0; i < 2; ++i)
#pragma unroll
        for (int j = 0; j < 8; ++j)
#pragma unroll
            for (int q = 0; q < 4; ++q) acc[i][j][q] = 0.0f;

    issue(0, 0);
    CP_COMMIT();

    const int NC = K >> 5;
    for (int c = 0; c < NC; ++c) {
        if (c + 1 < NC) { issue((c + 1) & 1, (c + 1) << 5); CP_COMMIT(); CP_WAIT1(); }
        else            { CP_WAIT0(); }
        __syncthreads();

        const uint32_t s = sb + (uint32_t)(c & 1) * STG2;
#pragma unroll
        for (int kh = 0; kh < 2; ++kh) {
            const uint32_t ka = kh * 32;     // 16 k-elements = 32 bytes

            uint32_t ah[2][4], al[2][4];
#pragma unroll
            for (int mi = 0; mi < 2; ++mi) {
                ldsm4(ah[mi], s + a_off[mi] + ka);
                ldsm4(al[mi], s + SLOT2 + a_off[mi] + ka);
            }
#pragma unroll
            for (int nb = 0; nb < 4; ++nb) {
                uint32_t bh[4], bl[4];
                ldsm4(bh, s + 2 * SLOT2 + b_off[nb] + ka);
                ldsm4(bl, s + 3 * SLOT2 + b_off[nb] + ka);
#pragma unroll
                for (int mi = 0; mi < 2; ++mi) {
                    mma16816(acc[mi][nb * 2],     ah[mi], bh[0], bh[1]);
                    mma16816(acc[mi][nb * 2 + 1], ah[mi], bh[2], bh[3]);
                    mma16816(acc[mi][nb * 2],     al[mi], bh[0], bh[1]);
                    mma16816(acc[mi][nb * 2 + 1], al[mi], bh[2], bh[3]);
                    mma16816(acc[mi][nb * 2],     ah[mi], bl[0], bl[1]);
                    mma16816(acc[mi][nb * 2 + 1], ah[mi], bl[2], bl[3]);
                }
            }
        }
        __syncthreads();
    }

#pragma unroll
    for (int mi = 0; mi < 2; ++mi)
#pragma unroll
        for (int nf = 0; nf < 8; ++nf) {
            const int m = m0 + wm * 32 + mi * 16 + gid;
            const int n = n0 + wn * 64 + nf * 8 + tig * 2;
            p.store2(bz, m,     n, acc[mi][nf][0], acc[mi][nf][1]);
            p.store2(bz, m + 8, n, acc[mi][nf][2], acc[mi][nf][3]);
        }
}

// ---------------- fused flash attention (unchanged) ---------------------------
#define KH_OFF 0u
#define KL_OFF 17408u
#define VH_OFF 34816u
#define VL_OFF 53248u
#define FSTAGE 71680u
#define FSMEM  (2 * 71680)
#define SCL2   (ATTN_SCALE * 1.4426950408889634f)

__global__ __launch_bounds__(256, 1) void flash_attn()
{
    extern __shared__ __align__(1024) char fsm[];
    const uint32_t sb = smem_u32(fsm);
    const int tid  = threadIdx.x;
    const int lane = tid & 31, wid = tid >> 5;
    const int gid = lane >> 2, tig = lane & 3;
    const int bz = blockIdx.y;
    const int q0 = blockIdx.x * 128 + wid * 16 + gid;

    const bf16* Kh = g_kh  + (size_t)bz * NS * ND;
    const bf16* Kl = g_kl  + (size_t)bz * NS * ND;
    const bf16* Vh = g_vTh + (size_t)bz * ND * NS;
    const bf16* Vl = g_vTl + (size_t)bz * ND * NS;

    uint32_t qh[8][4], ql[8][4];
    {
        const bf16* Qh = g_qh + ((size_t)bz * NS + q0) * ND;
        const bf16* Ql = g_ql + ((size_t)bz * NS + q0) * ND;
#pragma unroll
        for (int kc = 0; kc < 8; ++kc) {
            const int k0 = kc * 16 + tig * 2;
            qh[kc][0] = *(const uint32_t*)(Qh + k0);
            qh[kc][1] = *(const uint32_t*)(Qh + 8 * ND + k0);
            qh[kc][2] = *(const uint32_t*)(Qh + k0 + 8);
            qh[kc][3] = *(const uint32_t*)(Qh + 8 * ND + k0 + 8);
            ql[kc][0] = *(const uint32_t*)(Ql + k0);
            ql[kc][1] = *(const uint32_t*)(Ql + 8 * ND + k0);
            ql[kc][2] = *(const uint32_t*)(Ql + k0 + 8);
            ql[kc][3] = *(const uint32_t*)(Ql + 8 * ND + k0 + 8);
        }
    }

    auto issue = [&](int st, int kv0) {
        const uint32_t s = sb + (uint32_t)st * FSTAGE;
#pragma unroll
        for (int i = 0; i < 4; ++i) {
            const int idx = tid + i * 256;
            {
                const int r = idx >> 4, c = idx & 15;
                CP16(s + KH_OFF + (uint32_t)(r * 272 + c * 16),
                     Kh + (size_t)(kv0 + r) * ND + c * 8);
                CP16(s + KL_OFF + (uint32_t)(r * 272 + c * 16),
                     Kl + (size_t)(kv0 + r) * ND + c * 8);
            }
            {
                const int r = idx >> 3, c = idx & 7;
                CP16(s + VH_OFF + (uint32_t)(r * 144 + c * 16),
                     Vh + (size_t)r * NS + kv0 + c * 8);
                CP16(s + VL_OFF + (uint32_t)(r * 144 + c * 16),
                     Vl + (size_t)r * NS + kv0 + c * 8);
            }
        }
    };

    float oacc[16][4];
#pragma unroll
    for (int i = 0; i < 16; ++i)
#pragma unroll
        for (int q = 0; q < 4; ++q) oacc[i][q] = 0.0f;
    float m0 = -1e30f, m1 = -1e30f, l0 = 0.0f, l1 = 0.0f;

    issue(0, 0);
    CP_COMMIT();

    for (int t = 0; t < 16; ++t) {
        if (t + 1 < 16) { issue((t + 1) & 1, (t + 1) * 64); CP_COMMIT(); CP_WAIT1(); }
        else            { CP_WAIT0(); }
        __syncthreads();

        const char* stg = fsm + (size_t)(t & 1) * FSTAGE;

        float sacc[8][4];
#pragma unroll
        for (int nf = 0; nf < 8; ++nf)
#pragma unroll
            for (int q = 0; q < 4; ++q) sacc[nf][q] = 0.0f;

#pragma unroll
        for (int kc = 0; kc < 8; ++kc)
#pragma unroll
            for (int nf = 0; nf < 8; ++nf) {
                const char* pb = stg + KH_OFF + (nf * 8 + gid) * 272 + kc * 32 + tig * 4;
                const uint32_t bh0 = *(const uint32_t*)(pb);
                const uint32_t bh1 = *(const uint32_t*)(pb + 16);
                const uint32_t bl0 = *(const uint32_t*)(pb + (KL_OFF - KH_OFF));
                const uint32_t bl1 = *(const uint32_t*)(pb + (KL_OFF - KH_OFF) + 16);
                mma16816(sacc[nf], qh[kc], bh0, bh1);
                mma16816(sacc[nf], ql[kc], bh0, bh1);
                mma16816(sacc[nf], qh[kc], bl0, bl1);
            }

        float rm0 = -1e30f, rm1 = -1e30f;
#pragma unroll
        for (int nf = 0; nf < 8; ++nf) {
            sacc[nf][0] *= SCL2; sacc[nf][1] *= SCL2;
            sacc[nf][2] *= SCL2; sacc[nf][3] *= SCL2;
            rm0 = fmaxf(rm0, fmaxf(sacc[nf][0], sacc[nf][1]));
            rm1 = fmaxf(rm1, fmaxf(sacc[nf][2], sacc[nf][3]));
        }
        rm0 = fmaxf(rm0, __shfl_xor_sync(0xffffffffu, rm0, 1));
        rm0 = fmaxf(rm0, __shfl_xor_sync(0xffffffffu, rm0, 2));
        rm1 = fmaxf(rm1, __shfl_xor_sync(0xffffffffu, rm1, 1));
        rm1 = fmaxf(rm1, __shfl_xor_sync(0xffffffffu, rm1, 2));

        const float mn0 = fmaxf(m0, rm0), mn1 = fmaxf(m1, rm1);
        const float al0 = exp2f(m0 - mn0), al1 = exp2f(m1 - mn1);
        m0 = mn0; m1 = mn1;

        float sum0 = 0.0f, sum1 = 0.0f;
#pragma unroll
        for (int nf = 0; nf < 8; ++nf) {
            sacc[nf][0] = exp2f(sacc[nf][0] - m0);
            sacc[nf][1] = exp2f(sacc[nf][1] - m0);
            sacc[nf][2] = exp2f(sacc[nf][2] - m1);
            sacc[nf][3] = exp2f(sacc[nf][3] - m1);
            sum0 += sacc[nf][0] + sacc[nf][1];
            sum1 += sacc[nf][2] + sacc[nf][3];
        }
        sum0 += __shfl_xor_sync(0xffffffffu, sum0, 1);
        sum0 += __shfl_xor_sync(0xffffffffu, sum0, 2);
        sum1 += __shfl_xor_sync(0xffffffffu, sum1, 1);
        sum1 += __shfl_xor_sync(0xffffffffu, sum1, 2);
        l0 = l0 * al0 + sum0;
        l1 = l1 * al1 + sum1;

#pragma unroll
        for (int nf = 0; nf < 16; ++nf) {
            oacc[nf][0] *= al0; oacc[nf][1] *= al0;
            oacc[nf][2] *= al1; oacc[nf][3] *= al1;
        }

#pragma unroll
        for (int kc = 0; kc < 4; ++kc) {
            uint32_t ph[4], pl[4];
            {
                bf16 a0, b0, a1, b1;
                split(sacc[2 * kc][0], a0, b0); split(sacc[2 * kc][1], a1, b1);
                ph[0] = pk(a0, a1); pl[0] = pk(b0, b1);
                split(sacc[2 * kc][2], a0, b0); split(sacc[2 * kc][3], a1, b1);
                ph[1] = pk(a0, a1); pl[1] = pk(b0, b1);
                split(sacc[2 * kc + 1][0], a0, b0); split(sacc[2 * kc + 1][1], a1, b1);
                ph[2] = pk(a0, a1); pl[2] = pk(b0, b1);
                split(sacc[2 * kc + 1][2], a0, b0); split(sacc[2 * kc + 1][3], a1, b1);
                ph[3] = pk(a0, a1); pl[3] = pk(b0, b1);
            }
#pragma unroll
            for (int nf = 0; nf < 16; ++nf) {
                const char* pb = stg + VH_OFF + (nf * 8 + gid) * 144 + kc * 32 + tig * 4;
                const uint32_t vb0 = *(const uint32_t*)(pb);
                const uint32_t vb1 = *(const uint32_t*)(pb + 16);
                const uint32_t vc0 = *(const uint32_t*)(pb + (VL_OFF - VH_OFF));
                const uint32_t vc1 = *(const uint32_t*)(pb + (VL_OFF - VH_OFF) + 16);
                mma16816(oacc[nf], ph, vb0, vb1);
                mma16816(oacc[nf], pl, vb0, vb1);
                mma16816(oacc[nf], ph, vc0, vc1);
            }
        }
        __syncthreads();
    }

    const float inv0 = 1.0f / l0, inv1 = 1.0f / l1;
    const int b = bz >> 4, h = bz & 15;
    const size_t base = ((size_t)(b * NS + q0)) * NE + h * ND;
#pragma unroll
    for (int nf = 0; nf < 16; ++nf) {
        const int d = nf * 8 + tig * 2;
        bf16 h0, lo0, h1, lo1;
        split(oacc[nf][0] * inv0, h0, lo0); split(oacc[nf][1] * inv0, h1, lo1);
        *(uint32_t*)(g_ch + base + d) = pk(h0, h1);
        *(uint32_t*)(g_cl + base + d) = pk(lo0, lo1);
        split(oacc[nf][2] * inv1, h0, lo0); split(oacc[nf][3] * inv1, h1, lo1);
        *(uint32_t*)(g_ch + base + 8 * NE + d) = pk(h0, h1);
        *(uint32_t*)(g_cl + base + 8 * NE + d) = pk(lo0, lo1);
    }
}

// ---------------- fp32 -> bf16 hi/lo conversion ------------------------------
__global__ __launch_bounds__(256) void cvt_k(const float4* __restrict__ src,
                                             int n4, int sel)
{
    uint2* dh; uint2* dl;
    if (sel == 0)      { dh = (uint2*)g_xh;  dl = (uint2*)g_xl;  }
    else if (sel == 1) { dh = (uint2*)g_wih; dl = (uint2*)g_wil; }
    else               { dh = (uint2*)g_woh; dl = (uint2*)g_wol; }

    const int i = blockIdx.x * 256 + threadIdx.x;
    if (i >= n4) return;
    const float4 v = src[i];
    bf16 h0, l0, h1, l1, h2, l2, h3, l3;
    split(v.x, h0, l0); split(v.y, h1, l1);
    split(v.z, h2, l2); split(v.w, h3, l3);
    dh[i] = make_uint2(pk(h0, h1), pk(h2, h3));
    dl[i] = make_uint2(pk(l0, l1), pk(l2, l3));
}

// ---------------- host --------------------------------------------------------
extern "C" void kernel_launch(void* const* d_in, const int* in_sizes, int n_in,
                              void* d_out, int out_size)
{
    (void)in_sizes; (void)n_in; (void)out_size;
    const float* x  = (const float*)d_in[0];
    const float* wi = (const float*)d_in[1];
    const float* bi = (const float*)d_in[2];
    const float* wo = (const float*)d_in[3];
    const float* bo = (const float*)d_in[4];
    float* out = (float*)d_out;

    cudaFuncSetAttribute(gemm_mma<PQkv>, cudaFuncAttributeMaxDynamicSharedMemorySize, GSMEM);
    cudaFuncSetAttribute(gemm_mma<POut>, cudaFuncAttributeMaxDynamicSharedMemorySize, GSMEM);
    cudaFuncSetAttribute(flash_attn,     cudaFuncAttributeMaxDynamicSharedMemorySize, FSMEM);

    // 0) split external fp32 operands into bf16 hi/lo
    cvt_k<<<(NB*NS*NE/4 + 255) / 256, 256>>>((const float4*)x,  NB*NS*NE/4, 0);
    cvt_k<<<(3*NE*NE/4  + 255) / 256, 256>>>((const float4*)wi, 3*NE*NE/4,  1);
    cvt_k<<<(NE*NE/4    + 255) / 256, 256>>>((const float4*)wo, NE*NE/4,    2);

    // 1) QKV projection (+bias, head scatter, V transposed)
    gemm_mma<PQkv><<<dim3(48, 32, 1), 256, GSMEM>>>(PQkv{bi}, NE);

    // 2-4) fused attention: scores + softmax + P·V
    flash_attn<<<dim3(NS / 128, NB * NH), 256, FSMEM>>>();

    // 5) out = ctx W_out^T + bias
    gemm_mma<POut><<<dim3(16, 32, 1), 256, GSMEM>>>(POut{bo, out}, NE);
}

// round 10
// speedup vs baseline: 4.0866x; 1.4887x over previous
#include <cuda_runtime.h>
#include <cuda_fp16.h>
#include <math.h>
#include <stdint.h>

#define NB 4
#define NS 1024
#define NE 2048
#define NH 16
#define ND 128
#define ATTN_SCALE 0.08838834764831845f

typedef __half hf;

// ---------------- scratch (device globals; referenced ONLY from device code) --
__device__ __align__(256) hf g_xh [(size_t)NB*NS*NE];
__device__ __align__(256) hf g_xl [(size_t)NB*NS*NE];
__device__ __align__(256) hf g_wih[(size_t)3*NE*NE];
__device__ __align__(256) hf g_woh[(size_t)NE*NE];
__device__ __align__(256) hf g_qh [(size_t)NB*NH*NS*ND];
__device__ __align__(256) hf g_ql [(size_t)NB*NH*NS*ND];
__device__ __align__(256) hf g_kh [(size_t)NB*NH*NS*ND];
__device__ __align__(256) hf g_vTh[(size_t)NB*NH*ND*NS];   // [b,h,d,s]
__device__ __align__(256) hf g_ch [(size_t)NB*NS*NE];
__device__ __align__(256) hf g_cl [(size_t)NB*NS*NE];

// ---------------- PTX helpers ------------------------------------------------
__device__ __forceinline__ uint32_t smem_u32(const void* p) {
    uint32_t a;
    asm("{ .reg .u64 t; cvta.to.shared.u64 t, %1; cvt.u32.u64 %0, t; }" : "=r"(a) : "l"(p));
    return a;
}

#define CP16(dst, src) \
    asm volatile("cp.async.cg.shared.global [%0], [%1], 16;" :: "r"(dst), "l"(src) : "memory")
#define CP_COMMIT() asm volatile("cp.async.commit_group;" ::: "memory")
#define CP_WAIT1()  asm volatile("cp.async.wait_group 1;" ::: "memory")
#define CP_WAIT0()  asm volatile("cp.async.wait_group 0;" ::: "memory")

__device__ __forceinline__ void ldsm4(uint32_t* r, uint32_t a) {
    asm volatile("ldmatrix.sync.aligned.m8n8.x4.shared.b16 {%0,%1,%2,%3}, [%4];"
                 : "=r"(r[0]), "=r"(r[1]), "=r"(r[2]), "=r"(r[3]) : "r"(a));
}
__device__ __forceinline__ void mma16816(float* d, const uint32_t* a, uint32_t b0, uint32_t b1) {
    asm volatile(
        "mma.sync.aligned.m16n8k16.row.col.f32.f16.f16.f32 "
        "{%0,%1,%2,%3}, {%4,%5,%6,%7}, {%8,%9}, {%0,%1,%2,%3};"
        : "+f"(d[0]), "+f"(d[1]), "+f"(d[2]), "+f"(d[3])
        : "r"(a[0]), "r"(a[1]), "r"(a[2]), "r"(a[3]), "r"(b0), "r"(b1));
}

__device__ __forceinline__ uint32_t pk(hf a, hf b) {
    return (uint32_t)__half_as_ushort(a) | ((uint32_t)__half_as_ushort(b) << 16);
}
__device__ __forceinline__ void split(float v, hf& h, hf& l) {
    h = __float2half_rn(v);
    l = __float2half_rn(v - __half2float(h));
}

// ---------------- operand-source / epilogue param structs -------------------
// ptr(w, bz): w=0 Ah, 1 Al, 2 Bh.  All operands [rows][K] row-major.
struct PQkv {
    const float* bias;
    __device__ const hf* ptr(int w, int) const {
        return w == 0 ? g_xh : w == 1 ? g_xl : g_wih;
    }
    __device__ __forceinline__ void store2(int, int m, int n, float v0, float v1) const {
        v0 += bias[n]; v1 += bias[n + 1];
        const int which = n >> 11;
        const int e = n & 2047, h = e >> 7, d = e & 127;
        const int b = m >> 10, s = m & 1023;
        if (which == 0) {                       // Q: split (A of S-GEMM)
            hf h0, l0, h1, l1;
            split(v0, h0, l0); split(v1, h1, l1);
            const size_t off = ((size_t)((b * NH + h) * NS + s)) * ND + d;
            *(uint32_t*)(g_qh + off) = pk(h0, h1);
            *(uint32_t*)(g_ql + off) = pk(l0, l1);
        } else if (which == 1) {                // K: hi only (B of S-GEMM)
            const size_t off = ((size_t)((b * NH + h) * NS + s)) * ND + d;
            *(uint32_t*)(g_kh + off) = pk(__float2half_rn(v0), __float2half_rn(v1));
        } else {                                // V: hi only, transposed [d][s]
            const size_t off = ((size_t)((b * NH + h) * ND + d)) * NS + s;
            g_vTh[off]      = __float2half_rn(v0);
            g_vTh[off + NS] = __float2half_rn(v1);
        }
    }
};

struct POut {
    const float* bias;
    float* out;
    __device__ const hf* ptr(int w, int) const {
        return w == 0 ? g_ch : w == 1 ? g_cl : g_woh;
    }
    __device__ __forceinline__ void store2(int, int m, int n, float v0, float v1) const {
        float2 o = make_float2(v0 + bias[n], v1 + bias[n + 1]);
        *(float2*)(out + (size_t)m * NE + n) = o;
    }
};

// ---------------- fp16 A-split MMA GEMM (projections) -------------------------
// C[128,128] = Ah·Bh^T + Al·Bh^T, fp32 accum. BK=32.
// 3 tiles/stage (Ah, Al, Bh), 128 rows x 80B pitch = 30KB/stage; 60KB dynamic.
#define SLOT2  10240u
#define STG2   30720u
#define GSMEM  (2 * 30720)

template <class P>
__global__ __launch_bounds__(256, 2) void gemm_mma(P p, int K)
{
    extern __shared__ __align__(1024) char gsm[];
    const uint32_t sb = smem_u32(gsm);
    const int tid  = threadIdx.x;
    const int lane = tid & 31, wid = tid >> 5;
    const int wm = wid >> 1, wn = wid & 1;       // 4x2 warp grid, warp tile 32x64
    const int gid = lane >> 2, tig = lane & 3;
    const int bz = blockIdx.z;
    const int m0 = blockIdx.y * 128, n0 = blockIdx.x * 128;

    const hf* ah_p = p.ptr(0, bz);
    const hf* al_p = p.ptr(1, bz);
    const hf* bh_p = p.ptr(2, bz);

    auto issue = [&](int st, int kt) {
        const uint32_t s = sb + (uint32_t)st * STG2;
#pragma unroll
        for (int i = 0; i < 2; ++i) {
            const int idx = tid + i * 256;
            const int r = idx >> 2, c = idx & 3;
            const uint32_t d = (uint32_t)(r * 80 + c * 16);
            const size_t  o = (size_t)r * K + kt + c * 8;
            CP16(s + d,             ah_p + (size_t)m0 * K + o);
            CP16(s + SLOT2 + d,     al_p + (size_t)m0 * K + o);
            CP16(s + 2 * SLOT2 + d, bh_p + (size_t)n0 * K + o);
        }
    };

    uint32_t a_off[2], b_off[4];
#pragma unroll
    for (int mi = 0; mi < 2; ++mi)
        a_off[mi] = (uint32_t)((wm * 32 + mi * 16 + (lane & 15)) * 80 + (lane >> 4) * 16);
#pragma unroll
    for (int nb = 0; nb < 4; ++nb) {
        const int rw = wn * 64 + nb * 16 + (lane & 7) + ((lane >> 4) & 1) * 8;
        b_off[nb] = (uint32_t)(rw * 80 + ((lane >> 3) & 1) * 16);
    }

    float acc[2][8][4];
#pragma unroll
    for (int i = 0; i < 2; ++i)
#pragma unroll
        for (int j = 0; j < 8; ++j)
#pragma unroll
            for (int q = 0; q < 4; ++q) acc[i][j][q] = 0.0f;

    issue(0, 0);
    CP_COMMIT();

    const int NC = K >> 5;
    for (int c = 0; c < NC; ++c) {
        if (c + 1 < NC) { issue((c + 1) & 1, (c + 1) << 5); CP_COMMIT(); CP_WAIT1(); }
        else            { CP_WAIT0(); }
        __syncthreads();

        const uint32_t s = sb + (uint32_t)(c & 1) * STG2;
#pragma unroll
        for (int kh = 0; kh < 2; ++kh) {
            const uint32_t ka = kh * 32;

            uint32_t ah[2][4], al[2][4];
#pragma unroll
            for (int mi = 0; mi < 2; ++mi) {
                ldsm4(ah[mi], s + a_off[mi] + ka);
                ldsm4(al[mi], s + SLOT2 + a_off[mi] + ka);
            }
#pragma unroll
            for (int nb = 0; nb < 4; ++nb) {
                uint32_t bh[4];
                ldsm4(bh, s + 2 * SLOT2 + b_off[nb] + ka);
#pragma unroll
                for (int mi = 0; mi < 2; ++mi) {
                    mma16816(acc[mi][nb * 2],     ah[mi], bh[0], bh[1]);
                    mma16816(acc[mi][nb * 2 + 1], ah[mi], bh[2], bh[3]);
                    mma16816(acc[mi][nb * 2],     al[mi], bh[0], bh[1]);
                    mma16816(acc[mi][nb * 2 + 1], al[mi], bh[2], bh[3]);
                }
            }
        }
        __syncthreads();
    }

#pragma unroll
    for (int mi = 0; mi < 2; ++mi)
#pragma unroll
        for (int nf = 0; nf < 8; ++nf) {
            const int m = m0 + wm * 32 + mi * 16 + gid;
            const int n = n0 + wn * 64 + nf * 8 + tig * 2;
            p.store2(bz, m,     n, acc[mi][nf][0], acc[mi][nf][1]);
            p.store2(bz, m + 8, n, acc[mi][nf][2], acc[mi][nf][3]);
        }
}

// ---------------- fused flash attention (fp16, A-split) -----------------------
// S = Qh·Kh + Ql·Kh ; O += Ph·Vh + Pl·Vh. K and V hi-only.
#define KH_OFF 0u
#define VH_OFF 17408u
#define FSTAGE 35840u
#define FSMEM  (2 * 35840)
#define SCL2   (ATTN_SCALE * 1.4426950408889634f)

__global__ __launch_bounds__(256, 1) void flash_attn()
{
    extern __shared__ __align__(1024) char fsm[];
    const uint32_t sb = smem_u32(fsm);
    const int tid  = threadIdx.x;
    const int lane = tid & 31, wid = tid >> 5;
    const int gid = lane >> 2, tig = lane & 3;
    const int bz = blockIdx.y;
    const int q0 = blockIdx.x * 128 + wid * 16 + gid;

    const hf* Kh = g_kh  + (size_t)bz * NS * ND;
    const hf* Vh = g_vTh + (size_t)bz * ND * NS;

    uint32_t qh[8][4], ql[8][4];
    {
        const hf* Qh = g_qh + ((size_t)bz * NS + q0) * ND;
        const hf* Ql = g_ql + ((size_t)bz * NS + q0) * ND;
#pragma unroll
        for (int kc = 0; kc < 8; ++kc) {
            const int k0 = kc * 16 + tig * 2;
            qh[kc][0] = *(const uint32_t*)(Qh + k0);
            qh[kc][1] = *(const uint32_t*)(Qh + 8 * ND + k0);
            qh[kc][2] = *(const uint32_t*)(Qh + k0 + 8);
            qh[kc][3] = *(const uint32_t*)(Qh + 8 * ND + k0 + 8);
            ql[kc][0] = *(const uint32_t*)(Ql + k0);
            ql[kc][1] = *(const uint32_t*)(Ql + 8 * ND + k0);
            ql[kc][2] = *(const uint32_t*)(Ql + k0 + 8);
            ql[kc][3] = *(const uint32_t*)(Ql + 8 * ND + k0 + 8);
        }
    }

    auto issue = [&](int st, int kv0) {
        const uint32_t s = sb + (uint32_t)st * FSTAGE;
#pragma unroll
        for (int i = 0; i < 4; ++i) {
            const int idx = tid + i * 256;
            {   // K tile: 64 rows (s) x 128 d; pitch 272B
                const int r = idx >> 4, c = idx & 15;
                CP16(s + KH_OFF + (uint32_t)(r * 272 + c * 16),
                     Kh + (size_t)(kv0 + r) * ND + c * 8);
            }
            {   // V tile: 128 rows (d) x 64 s; pitch 144B
                const int r = idx >> 3, c = idx & 7;
                CP16(s + VH_OFF + (uint32_t)(r * 144 + c * 16),
                     Vh + (size_t)r * NS + kv0 + c * 8);
            }
        }
    };

    float oacc[16][4];
#pragma unroll
    for (int i = 0; i < 16; ++i)
#pragma unroll
        for (int q = 0; q < 4; ++q) oacc[i][q] = 0.0f;
    float m0 = -1e30f, m1 = -1e30f, l0 = 0.0f, l1 = 0.0f;

    issue(0, 0);
    CP_COMMIT();

    for (int t = 0; t < 16; ++t) {
        if (t + 1 < 16) { issue((t + 1) & 1, (t + 1) * 64); CP_COMMIT(); CP_WAIT1(); }
        else            { CP_WAIT0(); }
        __syncthreads();

        const char* stg = fsm + (size_t)(t & 1) * FSTAGE;

        float sacc[8][4];
#pragma unroll
        for (int nf = 0; nf < 8; ++nf)
#pragma unroll
            for (int q = 0; q < 4; ++q) sacc[nf][q] = 0.0f;

#pragma unroll
        for (int kc = 0; kc < 8; ++kc)
#pragma unroll
            for (int nf = 0; nf < 8; ++nf) {
                const char* pb = stg + KH_OFF + (nf * 8 + gid) * 272 + kc * 32 + tig * 4;
                const uint32_t bh0 = *(const uint32_t*)(pb);
                const uint32_t bh1 = *(const uint32_t*)(pb + 16);
                mma16816(sacc[nf], qh[kc], bh0, bh1);
                mma16816(sacc[nf], ql[kc], bh0, bh1);
            }

        float rm0 = -1e30f, rm1 = -1e30f;
#pragma unroll
        for (int nf = 0; nf < 8; ++nf) {
            sacc[nf][0] *= SCL2; sacc[nf][1] *= SCL2;
            sacc[nf][2] *= SCL2; sacc[nf][3] *= SCL2;
            rm0 = fmaxf(rm0, fmaxf(sacc[nf][0], sacc[nf][1]));
            rm1 = fmaxf(rm1, fmaxf(sacc[nf][2], sacc[nf][3]));
        }
        rm0 = fmaxf(rm0, __shfl_xor_sync(0xffffffffu, rm0, 1));
        rm0 = fmaxf(rm0, __shfl_xor_sync(0xffffffffu, rm0, 2));
        rm1 = fmaxf(rm1, __shfl_xor_sync(0xffffffffu, rm1, 1));
        rm1 = fmaxf(rm1, __shfl_xor_sync(0xffffffffu, rm1, 2));

        const float mn0 = fmaxf(m0, rm0), mn1 = fmaxf(m1, rm1);
        const float al0 = exp2f(m0 - mn0), al1 = exp2f(m1 - mn1);
        m0 = mn0; m1 = mn1;

        float sum0 = 0.0f, sum1 = 0.0f;
#pragma unroll
        for (int nf = 0; nf < 8; ++nf) {
            sacc[nf][0] = exp2f(sacc[nf][0] - m0);
            sacc[nf][1] = exp2f(sacc[nf][1] - m0);
            sacc[nf][2] = exp2f(sacc[nf][2] - m1);
            sacc[nf][3] = exp2f(sacc[nf][3] - m1);
            sum0 += sacc[nf][0] + sacc[nf][1];
            sum1 += sacc[nf][2] + sacc[nf][3];
        }
        sum0 += __shfl_xor_sync(0xffffffffu, sum0, 1);
        sum0 += __shfl_xor_sync(0xffffffffu, sum0, 2);
        sum1 += __shfl_xor_sync(0xffffffffu, sum1, 1);
        sum1 += __shfl_xor_sync(0xffffffffu, sum1, 2);
        l0 = l0 * al0 + sum0;
        l1 = l1 * al1 + sum1;

#pragma unroll
        for (int nf = 0; nf < 16; ++nf) {
            oacc[nf][0] *= al0; oacc[nf][1] *= al0;
            oacc[nf][2] *= al1; oacc[nf][3] *= al1;
        }

#pragma unroll
        for (int kc = 0; kc < 4; ++kc) {
            uint32_t ph[4], pl[4];
            {
                hf a0, b0, a1, b1;
                split(sacc[2 * kc][0], a0, b0); split(sacc[2 * kc][1], a1, b1);
                ph[0] = pk(a0, a1); pl[0] = pk(b0, b1);
                split(sacc[2 * kc][2], a0, b0); split(sacc[2 * kc][3], a1, b1);
                ph[1] = pk(a0, a1); pl[1] = pk(b0, b1);
                split(sacc[2 * kc + 1][0], a0, b0); split(sacc[2 * kc + 1][1], a1, b1);
                ph[2] = pk(a0, a1); pl[2] = pk(b0, b1);
                split(sacc[2 * kc + 1][2], a0, b0); split(sacc[2 * kc + 1][3], a1, b1);
                ph[3] = pk(a0, a1); pl[3] = pk(b0, b1);
            }
#pragma unroll
            for (int nf = 0; nf < 16; ++nf) {
                const char* pb = stg + VH_OFF + (nf * 8 + gid) * 144 + kc * 32 + tig * 4;
                const uint32_t vb0 = *(const uint32_t*)(pb);
                const uint32_t vb1 = *(const uint32_t*)(pb + 16);
                mma16816(oacc[nf], ph, vb0, vb1);
                mma16816(oacc[nf], pl, vb0, vb1);
            }
        }
        __syncthreads();
    }

    // ---- epilogue: normalize, split, store ctx hi/lo ----
    const float inv0 = 1.0f / l0, inv1 = 1.0f / l1;
    const int b = bz >> 4, h = bz & 15;
    const size_t base = ((size_t)(b * NS + q0)) * NE + h * ND;
#pragma unroll
    for (int nf = 0; nf < 16; ++nf) {
        const int d = nf * 8 + tig * 2;
        hf h0, lo0, h1, lo1;
        split(oacc[nf][0] * inv0, h0, lo0); split(oacc[nf][1] * inv0, h1, lo1);
        *(uint32_t*)(g_ch + base + d) = pk(h0, h1);
        *(uint32_t*)(g_cl + base + d) = pk(lo0, lo1);
        split(oacc[nf][2] * inv1, h0, lo0); split(oacc[nf][3] * inv1, h1, lo1);
        *(uint32_t*)(g_ch + base + 8 * NE + d) = pk(h0, h1);
        *(uint32_t*)(g_cl + base + 8 * NE + d) = pk(lo0, lo1);
    }
}

// ---------------- fp32 -> fp16 conversion -------------------------------------
// sel 0: x -> xh + xl (A-split). sel 1: wi -> wih (hi only). sel 2: wo -> woh.
__global__ __launch_bounds__(256) void cvt_k(const float4* __restrict__ src,
                                             int n4, int sel)
{
    const int i = blockIdx.x * 256 + threadIdx.x;
    if (i >= n4) return;
    const float4 v = src[i];

    if (sel == 0) {
        hf h0, l0, h1, l1, h2, l2, h3, l3;
        split(v.x, h0, l0); split(v.y, h1, l1);
        split(v.z, h2, l2); split(v.w, h3, l3);
        ((uint2*)g_xh)[i] = make_uint2(pk(h0, h1), pk(h2, h3));
        ((uint2*)g_xl)[i] = make_uint2(pk(l0, l1), pk(l2, l3));
    } else {
        hf* dst = sel == 1 ? g_wih : g_woh;
        ((uint2*)dst)[i] = make_uint2(
            pk(__float2half_rn(v.x), __float2half_rn(v.y)),
            pk(__float2half_rn(v.z), __float2half_rn(v.w)));
    }
}

// ---------------- host --------------------------------------------------------
extern "C" void kernel_launch(void* const* d_in, const int* in_sizes, int n_in,
                              void* d_out, int out_size)
{
    (void)in_sizes; (void)n_in; (void)out_size;
    const float* x  = (const float*)d_in[0];
    const float* wi = (const float*)d_in[1];
    const float* bi = (const float*)d_in[2];
    const float* wo = (const float*)d_in[3];
    const float* bo = (const float*)d_in[4];
    float* out = (float*)d_out;

    cudaFuncSetAttribute(gemm_mma<PQkv>, cudaFuncAttributeMaxDynamicSharedMemorySize, GSMEM);
    cudaFuncSetAttribute(gemm_mma<POut>, cudaFuncAttributeMaxDynamicSharedMemorySize, GSMEM);
    cudaFuncSetAttribute(flash_attn,     cudaFuncAttributeMaxDynamicSharedMemorySize, FSMEM);

    // 0) convert external fp32 operands to fp16 (x split, weights hi-only)
    cvt_k<<<(NB*NS*NE/4 + 255) / 256, 256>>>((const float4*)x,  NB*NS*NE/4, 0);
    cvt_k<<<(3*NE*NE/4  + 255) / 256, 256>>>((const float4*)wi, 3*NE*NE/4,  1);
    cvt_k<<<(NE*NE/4    + 255) / 256, 256>>>((const float4*)wo, NE*NE/4,    2);

    // 1) QKV projection (+bias, head scatter, V transposed)
    gemm_mma<PQkv><<<dim3(48, 32, 1), 256, GSMEM>>>(PQkv{bi}, NE);

    // 2-4) fused attention: scores + softmax + P·V
    flash_attn<<<dim3(NS / 128, NB * NH), 256, FSMEM>>>();

    // 5) out = ctx W_out^T + bias
    gemm_mma<POut><<<dim3(16, 32, 1), 256, GSMEM>>>(POut{bo, out}, NE);
}

// round 11
// speedup vs baseline: 4.5595x; 1.1157x over previous
#include <cuda_runtime.h>
#include <cuda_fp16.h>
#include <math.h>
#include <stdint.h>

#define NB 4
#define NS 1024
#define NE 2048
#define NH 16
#define ND 128
#define ATTN_SCALE 0.08838834764831845f

typedef __half hf;

// ---------------- scratch (device globals; referenced ONLY from device code) --
__device__ __align__(256) hf g_xh [(size_t)NB*NS*NE];
__device__ __align__(256) hf g_xl [(size_t)NB*NS*NE];
__device__ __align__(256) hf g_wih[(size_t)3*NE*NE];
__device__ __align__(256) hf g_woh[(size_t)NE*NE];
__device__ __align__(256) hf g_qh [(size_t)NB*NH*NS*ND];
__device__ __align__(256) hf g_ql [(size_t)NB*NH*NS*ND];
__device__ __align__(256) hf g_kh [(size_t)NB*NH*NS*ND];
__device__ __align__(256) hf g_vTh[(size_t)NB*NH*ND*NS];   // [b,h,d,s]
__device__ __align__(256) hf g_ch [(size_t)NB*NS*NE];
__device__ __align__(256) hf g_cl [(size_t)NB*NS*NE];

// ---------------- PTX helpers ------------------------------------------------
__device__ __forceinline__ uint32_t smem_u32(const void* p) {
    uint32_t a;
    asm("{ .reg .u64 t; cvta.to.shared.u64 t, %1; cvt.u32.u64 %0, t; }" : "=r"(a) : "l"(p));
    return a;
}

#define CP16(dst, src) \
    asm volatile("cp.async.cg.shared.global [%0], [%1], 16;" :: "r"(dst), "l"(src) : "memory")
#define CP_COMMIT() asm volatile("cp.async.commit_group;" ::: "memory")
#define CP_WAIT1()  asm volatile("cp.async.wait_group 1;" ::: "memory")
#define CP_WAIT0()  asm volatile("cp.async.wait_group 0;" ::: "memory")

__device__ __forceinline__ void ldsm4(uint32_t* r, uint32_t a) {
    asm volatile("ldmatrix.sync.aligned.m8n8.x4.shared.b16 {%0,%1,%2,%3}, [%4];"
                 : "=r"(r[0]), "=r"(r[1]), "=r"(r[2]), "=r"(r[3]) : "r"(a));
}
__device__ __forceinline__ void mma16816(float* d, const uint32_t* a, uint32_t b0, uint32_t b1) {
    asm volatile(
        "mma.sync.aligned.m16n8k16.row.col.f32.f16.f16.f32 "
        "{%0,%1,%2,%3}, {%4,%5,%6,%7}, {%8,%9}, {%0,%1,%2,%3};"
        : "+f"(d[0]), "+f"(d[1]), "+f"(d[2]), "+f"(d[3])
        : "r"(a[0]), "r"(a[1]), "r"(a[2]), "r"(a[3]), "r"(b0), "r"(b1));
}

__device__ __forceinline__ uint32_t pk(hf a, hf b) {
    return (uint32_t)__half_as_ushort(a) | ((uint32_t)__half_as_ushort(b) << 16);
}
__device__ __forceinline__ void split(float v, hf& h, hf& l) {
    h = __float2half_rn(v);
    l = __float2half_rn(v - __half2float(h));
}

// ---------------- operand-source / epilogue param structs -------------------
struct PQkv {
    const float* bias;
    __device__ const hf* ptr(int w, int) const {
        return w == 0 ? g_xh : w == 1 ? g_xl : g_wih;
    }
    __device__ __forceinline__ void store2(int, int m, int n, float v0, float v1) const {
        v0 += bias[n]; v1 += bias[n + 1];
        const int which = n >> 11;
        const int e = n & 2047, h = e >> 7, d = e & 127;
        const int b = m >> 10, s = m & 1023;
        if (which == 0) {                       // Q: split (A of S-GEMM)
            hf h0, l0, h1, l1;
            split(v0, h0, l0); split(v1, h1, l1);
            const size_t off = ((size_t)((b * NH + h) * NS + s)) * ND + d;
            *(uint32_t*)(g_qh + off) = pk(h0, h1);
            *(uint32_t*)(g_ql + off) = pk(l0, l1);
        } else if (which == 1) {                // K: hi only
            const size_t off = ((size_t)((b * NH + h) * NS + s)) * ND + d;
            *(uint32_t*)(g_kh + off) = pk(__float2half_rn(v0), __float2half_rn(v1));
        } else {                                // V: hi only, transposed [d][s]
            const size_t off = ((size_t)((b * NH + h) * ND + d)) * NS + s;
            g_vTh[off]      = __float2half_rn(v0);
            g_vTh[off + NS] = __float2half_rn(v1);
        }
    }
};

struct POut {
    const float* bias;
    float* out;
    __device__ const hf* ptr(int w, int) const {
        return w == 0 ? g_ch : w == 1 ? g_cl : g_woh;
    }
    __device__ __forceinline__ void store2(int, int m, int n, float v0, float v1) const {
        float2 o = make_float2(v0 + bias[n], v1 + bias[n + 1]);
        *(float2*)(out + (size_t)m * NE + n) = o;
    }
};

// ---------------- fp16 A-split MMA GEMM (projections) -------------------------
// C[128,128] = Ah·Bh^T + Al·Bh^T, fp32 accum. BK=32.
// 3 tiles/substage (Ah, Al, Bh) x 80B pitch = 30KB; THREE pipeline stages
// (90KB dynamic, 2 CTAs/SM = 180KB). ONE __syncthreads per chunk: the stage
// written at iter c is the one whose reads finished at iter c-1, proven by
// the barrier at the top of iter c.
#define SLOT2  10240u
#define STG2   30720u
#define GSMEM  (3 * 30720)

template <class P>
__global__ __launch_bounds__(256, 2) void gemm_mma(P p, int K)
{
    extern __shared__ __align__(1024) char gsm[];
    const uint32_t sb = smem_u32(gsm);
    const int tid  = threadIdx.x;
    const int lane = tid & 31, wid = tid >> 5;
    const int wm = wid >> 1, wn = wid & 1;       // 4x2 warp grid, warp tile 32x64
    const int gid = lane >> 2, tig = lane & 3;
    const int bz = blockIdx.z;
    const int m0 = blockIdx.y * 128, n0 = blockIdx.x * 128;

    const hf* ah_p = p.ptr(0, bz);
    const hf* al_p = p.ptr(1, bz);
    const hf* bh_p = p.ptr(2, bz);

    auto issue = [&](int st, int kt) {
        const uint32_t s = sb + (uint32_t)st * STG2;
#pragma unroll
        for (int i = 0; i < 2; ++i) {
            const int idx = tid + i * 256;
            const int r = idx >> 2, c = idx & 3;
            const uint32_t d = (uint32_t)(r * 80 + c * 16);
            const size_t  o = (size_t)r * K + kt + c * 8;
            CP16(s + d,             ah_p + (size_t)m0 * K + o);
            CP16(s + SLOT2 + d,     al_p + (size_t)m0 * K + o);
            CP16(s + 2 * SLOT2 + d, bh_p + (size_t)n0 * K + o);
        }
    };

    uint32_t a_off[2], b_off[4];
#pragma unroll
    for (int mi = 0; mi < 2; ++mi)
        a_off[mi] = (uint32_t)((wm * 32 + mi * 16 + (lane & 15)) * 80 + (lane >> 4) * 16);
#pragma unroll
    for (int nb = 0; nb < 4; ++nb) {
        const int rw = wn * 64 + nb * 16 + (lane & 7) + ((lane >> 4) & 1) * 8;
        b_off[nb] = (uint32_t)(rw * 80 + ((lane >> 3) & 1) * 16);
    }

    float acc[2][8][4];
#pragma unroll
    for (int i = 0; i < 2; ++i)
#pragma unroll
        for (int j = 0; j < 8; ++j)
#pragma unroll
            for (int q = 0; q < 4; ++q) acc[i][j][q] = 0.0f;

    issue(0, 0);      CP_COMMIT();
    issue(1, 32);     CP_COMMIT();

    const int NC = K >> 5;
    int cs = 0;       // c % 3
    int ws = 2;       // (c+2) % 3
    for (int c = 0; c < NC; ++c) {
        if (c + 1 < NC) CP_WAIT1(); else CP_WAIT0();
        __syncthreads();

        const uint32_t s = sb + (uint32_t)cs * STG2;
#pragma unroll
        for (int kh = 0; kh < 2; ++kh) {
            const uint32_t ka = kh * 32;

            uint32_t ah[2][4], al[2][4];
#pragma unroll
            for (int mi = 0; mi < 2; ++mi) {
                ldsm4(ah[mi], s + a_off[mi] + ka);
                ldsm4(al[mi], s + SLOT2 + a_off[mi] + ka);
            }
#pragma unroll
            for (int nb = 0; nb < 4; ++nb) {
                uint32_t bh[4];
                ldsm4(bh, s + 2 * SLOT2 + b_off[nb] + ka);
#pragma unroll
                for (int mi = 0; mi < 2; ++mi) {
                    mma16816(acc[mi][nb * 2],     ah[mi], bh[0], bh[1]);
                    mma16816(acc[mi][nb * 2 + 1], ah[mi], bh[2], bh[3]);
                    mma16816(acc[mi][nb * 2],     al[mi], bh[0], bh[1]);
                    mma16816(acc[mi][nb * 2 + 1], al[mi], bh[2], bh[3]);
                }
            }
        }

        if (c + 2 < NC) { issue(ws, (c + 2) << 5); CP_COMMIT(); }
        if (++cs == 3) cs = 0;
        if (++ws == 3) ws = 0;
    }

#pragma unroll
    for (int mi = 0; mi < 2; ++mi)
#pragma unroll
        for (int nf = 0; nf < 8; ++nf) {
            const int m = m0 + wm * 32 + mi * 16 + gid;
            const int n = n0 + wn * 64 + nf * 8 + tig * 2;
            p.store2(bz, m,     n, acc[mi][nf][0], acc[mi][nf][1]);
            p.store2(bz, m + 8, n, acc[mi][nf][2], acc[mi][nf][3]);
        }
}

// ---------------- fused flash attention (fp16, A-split, 3-stage) --------------
#define KH_OFF 0u
#define VH_OFF 17408u
#define FSTAGE 35840u
#define FSMEM  (3 * 35840)
#define SCL2   (ATTN_SCALE * 1.4426950408889634f)

__global__ __launch_bounds__(256, 1) void flash_attn()
{
    extern __shared__ __align__(1024) char fsm[];
    const uint32_t sb = smem_u32(fsm);
    const int tid  = threadIdx.x;
    const int lane = tid & 31, wid = tid >> 5;
    const int gid = lane >> 2, tig = lane & 3;
    const int bz = blockIdx.y;
    const int q0 = blockIdx.x * 128 + wid * 16 + gid;

    const hf* Kh = g_kh  + (size_t)bz * NS * ND;
    const hf* Vh = g_vTh + (size_t)bz * ND * NS;

    uint32_t qh[8][4], ql[8][4];
    {
        const hf* Qh = g_qh + ((size_t)bz * NS + q0) * ND;
        const hf* Ql = g_ql + ((size_t)bz * NS + q0) * ND;
#pragma unroll
        for (int kc = 0; kc < 8; ++kc) {
            const int k0 = kc * 16 + tig * 2;
            qh[kc][0] = *(const uint32_t*)(Qh + k0);
            qh[kc][1] = *(const uint32_t*)(Qh + 8 * ND + k0);
            qh[kc][2] = *(const uint32_t*)(Qh + k0 + 8);
            qh[kc][3] = *(const uint32_t*)(Qh + 8 * ND + k0 + 8);
            ql[kc][0] = *(const uint32_t*)(Ql + k0);
            ql[kc][1] = *(const uint32_t*)(Ql + 8 * ND + k0);
            ql[kc][2] = *(const uint32_t*)(Ql + k0 + 8);
            ql[kc][3] = *(const uint32_t*)(Ql + 8 * ND + k0 + 8);
        }
    }

    auto issue = [&](int st, int kv0) {
        const uint32_t s = sb + (uint32_t)st * FSTAGE;
#pragma unroll
        for (int i = 0; i < 4; ++i) {
            const int idx = tid + i * 256;
            {   // K tile: 64 rows (s) x 128 d; pitch 272B
                const int r = idx >> 4, c = idx & 15;
                CP16(s + KH_OFF + (uint32_t)(r * 272 + c * 16),
                     Kh + (size_t)(kv0 + r) * ND + c * 8);
            }
            {   // V tile: 128 rows (d) x 64 s; pitch 144B
                const int r = idx >> 3, c = idx & 7;
                CP16(s + VH_OFF + (uint32_t)(r * 144 + c * 16),
                     Vh + (size_t)r * NS + kv0 + c * 8);
            }
        }
    };

    float oacc[16][4];
#pragma unroll
    for (int i = 0; i < 16; ++i)
#pragma unroll
        for (int q = 0; q < 4; ++q) oacc[i][q] = 0.0f;
    float m0 = -1e30f, m1 = -1e30f, l0 = 0.0f, l1 = 0.0f;

    issue(0, 0);   CP_COMMIT();
    issue(1, 64);  CP_COMMIT();

    int cs = 0, ws = 2;
    for (int t = 0; t < 16; ++t) {
        if (t + 1 < 16) CP_WAIT1(); else CP_WAIT0();
        __syncthreads();

        const char* stg = fsm + (size_t)cs * FSTAGE;

        float sacc[8][4];
#pragma unroll
        for (int nf = 0; nf < 8; ++nf)
#pragma unroll
            for (int q = 0; q < 4; ++q) sacc[nf][q] = 0.0f;

#pragma unroll
        for (int kc = 0; kc < 8; ++kc)
#pragma unroll
            for (int nf = 0; nf < 8; ++nf) {
                const char* pb = stg + KH_OFF + (nf * 8 + gid) * 272 + kc * 32 + tig * 4;
                const uint32_t bh0 = *(const uint32_t*)(pb);
                const uint32_t bh1 = *(const uint32_t*)(pb + 16);
                mma16816(sacc[nf], qh[kc], bh0, bh1);
                mma16816(sacc[nf], ql[kc], bh0, bh1);
            }

        float rm0 = -1e30f, rm1 = -1e30f;
#pragma unroll
        for (int nf = 0; nf < 8; ++nf) {
            sacc[nf][0] *= SCL2; sacc[nf][1] *= SCL2;
            sacc[nf][2] *= SCL2; sacc[nf][3] *= SCL2;
            rm0 = fmaxf(rm0, fmaxf(sacc[nf][0], sacc[nf][1]));
            rm1 = fmaxf(rm1, fmaxf(sacc[nf][2], sacc[nf][3]));
        }
        rm0 = fmaxf(rm0, __shfl_xor_sync(0xffffffffu, rm0, 1));
        rm0 = fmaxf(rm0, __shfl_xor_sync(0xffffffffu, rm0, 2));
        rm1 = fmaxf(rm1, __shfl_xor_sync(0xffffffffu, rm1, 1));
        rm1 = fmaxf(rm1, __shfl_xor_sync(0xffffffffu, rm1, 2));

        const float mn0 = fmaxf(m0, rm0), mn1 = fmaxf(m1, rm1);
        const float al0 = exp2f(m0 - mn0), al1 = exp2f(m1 - mn1);
        m0 = mn0; m1 = mn1;

        float sum0 = 0.0f, sum1 = 0.0f;
#pragma unroll
        for (int nf = 0; nf < 8; ++nf) {
            sacc[nf][0] = exp2f(sacc[nf][0] - m0);
            sacc[nf][1] = exp2f(sacc[nf][1] - m0);
            sacc[nf][2] = exp2f(sacc[nf][2] - m1);
            sacc[nf][3] = exp2f(sacc[nf][3] - m1);
            sum0 += sacc[nf][0] + sacc[nf][1];
            sum1 += sacc[nf][2] + sacc[nf][3];
        }
        sum0 += __shfl_xor_sync(0xffffffffu, sum0, 1);
        sum0 += __shfl_xor_sync(0xffffffffu, sum0, 2);
        sum1 += __shfl_xor_sync(0xffffffffu, sum1, 1);
        sum1 += __shfl_xor_sync(0xffffffffu, sum1, 2);
        l0 = l0 * al0 + sum0;
        l1 = l1 * al1 + sum1;

#pragma unroll
        for (int nf = 0; nf < 16; ++nf) {
            oacc[nf][0] *= al0; oacc[nf][1] *= al0;
            oacc[nf][2] *= al1; oacc[nf][3] *= al1;
        }

#pragma unroll
        for (int kc = 0; kc < 4; ++kc) {
            uint32_t ph[4], pl[4];
            {
                hf a0, b0, a1, b1;
                split(sacc[2 * kc][0], a0, b0); split(sacc[2 * kc][1], a1, b1);
                ph[0] = pk(a0, a1); pl[0] = pk(b0, b1);
                split(sacc[2 * kc][2], a0, b0); split(sacc[2 * kc][3], a1, b1);
                ph[1] = pk(a0, a1); pl[1] = pk(b0, b1);
                split(sacc[2 * kc + 1][0], a0, b0); split(sacc[2 * kc + 1][1], a1, b1);
                ph[2] = pk(a0, a1); pl[2] = pk(b0, b1);
                split(sacc[2 * kc + 1][2], a0, b0); split(sacc[2 * kc + 1][3], a1, b1);
                ph[3] = pk(a0, a1); pl[3] = pk(b0, b1);
            }
#pragma unroll
            for (int nf = 0; nf < 16; ++nf) {
                const char* pb = stg + VH_OFF + (nf * 8 + gid) * 144 + kc * 32 + tig * 4;
                const uint32_t vb0 = *(const uint32_t*)(pb);
                const uint32_t vb1 = *(const uint32_t*)(pb + 16);
                mma16816(oacc[nf], ph, vb0, vb1);
                mma16816(oacc[nf], pl, vb0, vb1);
            }
        }

        if (t + 2 < 16) { issue(ws, (t + 2) * 64); CP_COMMIT(); }
        if (++cs == 3) cs = 0;
        if (++ws == 3) ws = 0;
    }

    // ---- epilogue: normalize, split, store ctx hi/lo ----
    const float inv0 = 1.0f / l0, inv1 = 1.0f / l1;
    const int b = bz >> 4, h = bz & 15;
    const size_t base = ((size_t)(b * NS + q0)) * NE + h * ND;
#pragma unroll
    for (int nf = 0; nf < 16; ++nf) {
        const int d = nf * 8 + tig * 2;
        hf h0, lo0, h1, lo1;
        split(oacc[nf][0] * inv0, h0, lo0); split(oacc[nf][1] * inv0, h1, lo1);
        *(uint32_t*)(g_ch + base + d) = pk(h0, h1);
        *(uint32_t*)(g_cl + base + d) = pk(lo0, lo1);
        split(oacc[nf][2] * inv1, h0, lo0); split(oacc[nf][3] * inv1, h1, lo1);
        *(uint32_t*)(g_ch + base + 8 * NE + d) = pk(h0, h1);
        *(uint32_t*)(g_cl + base + 8 * NE + d) = pk(lo0, lo1);
    }
}

// ---------------- fp32 -> fp16 conversion -------------------------------------
__global__ __launch_bounds__(256) void cvt_k(const float4* __restrict__ src,
                                             int n4, int sel)
{
    const int i = blockIdx.x * 256 + threadIdx.x;
    if (i >= n4) return;
    const float4 v = src[i];

    if (sel == 0) {
        hf h0, l0, h1, l1, h2, l2, h3, l3;
        split(v.x, h0, l0); split(v.y, h1, l1);
        split(v.z, h2, l2); split(v.w, h3, l3);
        ((uint2*)g_xh)[i] = make_uint2(pk(h0, h1), pk(h2, h3));
        ((uint2*)g_xl)[i] = make_uint2(pk(l0, l1), pk(l2, l3));
    } else {
        hf* dst = sel == 1 ? g_wih : g_woh;
        ((uint2*)dst)[i] = make_uint2(
            pk(__float2half_rn(v.x), __float2half_rn(v.y)),
            pk(__float2half_rn(v.z), __float2half_rn(v.w)));
    }
}

// ---------------- host --------------------------------------------------------
extern "C" void kernel_launch(void* const* d_in, const int* in_sizes, int n_in,
                              void* d_out, int out_size)
{
    (void)in_sizes; (void)n_in; (void)out_size;
    const float* x  = (const float*)d_in[0];
    const float* wi = (const float*)d_in[1];
    const float* bi = (const float*)d_in[2];
    const float* wo = (const float*)d_in[3];
    const float* bo = (const float*)d_in[4];
    float* out = (float*)d_out;

    cudaFuncSetAttribute(gemm_mma<PQkv>, cudaFuncAttributeMaxDynamicSharedMemorySize, GSMEM);
    cudaFuncSetAttribute(gemm_mma<POut>, cudaFuncAttributeMaxDynamicSharedMemorySize, GSMEM);
    cudaFuncSetAttribute(flash_attn,     cudaFuncAttributeMaxDynamicSharedMemorySize, FSMEM);

    // 0) convert external fp32 operands to fp16 (x split, weights hi-only)
    cvt_k<<<(NB*NS*NE/4 + 255) / 256, 256>>>((const float4*)x,  NB*NS*NE/4, 0);
    cvt_k<<<(3*NE*NE/4  + 255) / 256, 256>>>((const float4*)wi, 3*NE*NE/4,  1);
    cvt_k<<<(NE*NE/4    + 255) / 256, 256>>>((const float4*)wo, NE*NE/4,    2);

    // 1) QKV projection (+bias, head scatter, V transposed)
    gemm_mma<PQkv><<<dim3(48, 32, 1), 256, GSMEM>>>(PQkv{bi}, NE);

    // 2-4) fused attention: scores + softmax + P·V
    flash_attn<<<dim3(NS / 128, NB * NH), 256, FSMEM>>>();

    // 5) out = ctx W_out^T + bias
    gemm_mma<POut><<<dim3(16, 32, 1), 256, GSMEM>>>(POut{bo, out}, NE);
}